// round 14
// baseline (speedup 1.0000x reference)
#include <cuda_runtime.h>
#include <cuda_fp16.h>
#include <cstdint>

#define NN 50000
#define EE 1600000
#define RR 8
#define DIN1 128
#define HH 64
#define OUTD 32
#define FULLMASK 0xffffffffu

// ---------------- scratch (static device globals; allocation-free) ----------------
__device__ __half   g_ta[(size_t)RR * NN * HH];        // layer-1 transformed feats (fp16)
__device__ __half   g_tc[(size_t)RR * NN * 2 * HH];    // mu/lv interleaved: row=128 halves
__device__ float    g_qd[2 * RR * NN];
__device__ float    g_kd[RR * NN];                     // layer-1 kd
__device__ float2   g_kd2[RR * NN];                    // (kd_mu, kd_lv)
__device__ float    g_wq[3 * RR * DIN1];               // set 0: layer1, 1: mu, 2: lv
__device__ float    g_wk[3 * RR * DIN1];
__device__ float    g_hidden[NN * HH];
__device__ int      g_off[NN + 1];
__device__ int      g_cursor[NN];
__device__ unsigned g_edges[EE];                       // src | (etype<<16)

// ---------------- CSR build ----------------
__global__ void k_zero_off() {
    int i = blockIdx.x * blockDim.x + threadIdx.x;
    if (i <= NN) g_off[i] = 0;
}

__global__ void k_hist(const int* __restrict__ dst) {
    int e = blockIdx.x * blockDim.x + threadIdx.x;
    if (e < EE) atomicAdd(&g_off[dst[e]], 1);
}

__global__ void k_scan() {
    __shared__ int wsum[32];
    const int tid = threadIdx.x, lane = tid & 31, wid = tid >> 5;
    int carry = 0;
    for (int base = 0; base < NN; base += 1024) {
        int i = base + tid;
        int v = (i < NN) ? g_off[i] : 0;
        int s = v;
        #pragma unroll
        for (int o = 1; o < 32; o <<= 1) {
            int t = __shfl_up_sync(FULLMASK, s, o);
            if (lane >= o) s += t;
        }
        if (lane == 31) wsum[wid] = s;
        __syncthreads();
        if (wid == 0) {
            int ws = wsum[lane];
            #pragma unroll
            for (int o = 1; o < 32; o <<= 1) {
                int t = __shfl_up_sync(FULLMASK, ws, o);
                if (lane >= o) ws += t;
            }
            wsum[lane] = ws;
        }
        __syncthreads();
        int excl = s - v + (wid ? wsum[wid - 1] : 0) + carry;
        if (i < NN) { g_off[i] = excl; g_cursor[i] = excl; }
        int total = wsum[31];
        __syncthreads();
        carry += total;
    }
    if (tid == 0) g_off[NN] = carry;
}

__global__ void k_scatter(const int* __restrict__ src, const int* __restrict__ dst,
                          const int* __restrict__ et) {
    int e = blockIdx.x * blockDim.x + threadIdx.x;
    if (e < EE) {
        int pos = atomicAdd(&g_cursor[dst[e]], 1);
        g_edges[pos] = (unsigned)src[e] | ((unsigned)et[e] << 16);
    }
}

// ---------------- all three wq/wk sets in one kernel (blockIdx.x = set) ----------------
__global__ void k_wqwk3(const float* __restrict__ W1, const float* __restrict__ q1,
                        const float* __restrict__ k1,
                        const float* __restrict__ Wmu, const float* __restrict__ qmu,
                        const float* __restrict__ kmu,
                        const float* __restrict__ Wlv, const float* __restrict__ qlv,
                        const float* __restrict__ klv) {
    const int set = blockIdx.x;
    const float* W = (set == 0) ? W1 : (set == 1) ? Wmu : Wlv;
    const float* q = (set == 0) ? q1 : (set == 1) ? qmu : qlv;
    const float* k = (set == 0) ? k1 : (set == 1) ? kmu : klv;
    const int Din = (set == 0) ? DIN1 : HH;
    __shared__ float qs[HH], ks[HH];
    if (threadIdx.x < HH) { qs[threadIdx.x] = q[threadIdx.x]; ks[threadIdx.x] = k[threadIdx.x]; }
    __syncthreads();
    for (int e = threadIdx.x; e < RR * Din; e += blockDim.x) {
        const float* w = W + (size_t)e * HH;
        float aq = 0.f, ak = 0.f;
        #pragma unroll 8
        for (int o = 0; o < HH; o++) { float wv = w[o]; aq += wv * qs[o]; ak += wv * ks[o]; }
        g_wq[set * RR * DIN1 + e] = aq;
        g_wk[set * RR * DIN1 + e] = ak;
    }
}

// ---------------- fp16 mma helpers ----------------
__device__ __forceinline__ unsigned packh2(float a, float b) {
    __half2 h = __floats2half2_rn(a, b);
    return *(unsigned*)&h;
}

__device__ __forceinline__ void mma_fp16(float* d, const unsigned* a, const unsigned* b) {
    asm volatile(
        "mma.sync.aligned.m16n8k16.row.col.f32.f16.f16.f32 "
        "{%0,%1,%2,%3}, {%4,%5,%6,%7}, {%8,%9}, {%0,%1,%2,%3};\n"
        : "+f"(d[0]), "+f"(d[1]), "+f"(d[2]), "+f"(d[3])
        : "r"(a[0]), "r"(a[1]), "r"(a[2]), "r"(a[3]), "r"(b[0]), "r"(b[1]));
}

// ---------------- GEMM layer 1 (fp16 mma, double-buffered): Ta = X @ W[r] ----------------
#define BM 128
#define BK 16
__global__ __launch_bounds__(256) void k_gemm(const float* __restrict__ X,
                                              const float* __restrict__ W,
                                              __half* __restrict__ T, int Din) {
    const int r  = blockIdx.y;
    const int m0 = blockIdx.x * BM;
    __shared__ unsigned As[2][BM][12];
    __shared__ unsigned Bs[2][8][HH + 8];
    const int tid  = threadIdx.x;
    const int warp = tid >> 5, lane = tid & 31;
    const int wm = (warp & 3) * 32;
    const int wn = (warp >> 2) * 32;
    const int gid = lane >> 2, tig = lane & 3;
    float acc[2][4][4] = {};
    const float* Wr = W + (size_t)r * Din * HH;

    const int a_row  = tid >> 1;
    const int a_half = tid & 1;
    const int b_kp   = tid >> 5;
    const int b_n    = (tid & 31) * 2;
    const int gm_a   = m0 + a_row;
    const int nk = Din / BK;

    float4 va0, va1;
    float2 r0, r1;
    {
        if (gm_a < NN) {
            const float* p = X + (size_t)gm_a * Din + a_half * 8;
            va0 = *(const float4*)p; va1 = *(const float4*)(p + 4);
        } else { va0 = make_float4(0.f,0.f,0.f,0.f); va1 = va0; }
        r0 = *(const float2*)(Wr + (size_t)(2 * b_kp)     * HH + b_n);
        r1 = *(const float2*)(Wr + (size_t)(2 * b_kp + 1) * HH + b_n);
    }
    {
        unsigned* ap = &As[0][a_row][a_half * 4];
        ap[0] = packh2(va0.x, va0.y); ap[1] = packh2(va0.z, va0.w);
        ap[2] = packh2(va1.x, va1.y); ap[3] = packh2(va1.z, va1.w);
        Bs[0][b_kp][b_n]     = packh2(r0.x, r1.x);
        Bs[0][b_kp][b_n + 1] = packh2(r0.y, r1.y);
    }
    __syncthreads();

    for (int kt = 0; kt < nk; kt++) {
        const int cur = kt & 1;
        if (kt + 1 < nk) {
            int k0 = (kt + 1) * BK;
            if (gm_a < NN) {
                const float* p = X + (size_t)gm_a * Din + k0 + a_half * 8;
                va0 = *(const float4*)p; va1 = *(const float4*)(p + 4);
            } else { va0 = make_float4(0.f,0.f,0.f,0.f); va1 = va0; }
            r0 = *(const float2*)(Wr + (size_t)(k0 + 2 * b_kp)     * HH + b_n);
            r1 = *(const float2*)(Wr + (size_t)(k0 + 2 * b_kp + 1) * HH + b_n);
        }
        {
            unsigned a[2][4], b[4][2];
            #pragma unroll
            for (int mf = 0; mf < 2; mf++) {
                int mr = wm + mf * 16;
                a[mf][0] = As[cur][mr + gid    ][tig];
                a[mf][1] = As[cur][mr + gid + 8][tig];
                a[mf][2] = As[cur][mr + gid    ][tig + 4];
                a[mf][3] = As[cur][mr + gid + 8][tig + 4];
            }
            #pragma unroll
            for (int nf = 0; nf < 4; nf++) {
                int nc = wn + nf * 8;
                b[nf][0] = Bs[cur][tig    ][nc + gid];
                b[nf][1] = Bs[cur][tig + 4][nc + gid];
            }
            #pragma unroll
            for (int mf = 0; mf < 2; mf++)
                #pragma unroll
                for (int nf = 0; nf < 4; nf++)
                    mma_fp16(acc[mf][nf], a[mf], b[nf]);
        }
        if (kt + 1 < nk) {
            const int nxt = (kt + 1) & 1;
            unsigned* ap = &As[nxt][a_row][a_half * 4];
            ap[0] = packh2(va0.x, va0.y); ap[1] = packh2(va0.z, va0.w);
            ap[2] = packh2(va1.x, va1.y); ap[3] = packh2(va1.z, va1.w);
            Bs[nxt][b_kp][b_n]     = packh2(r0.x, r1.x);
            Bs[nxt][b_kp][b_n + 1] = packh2(r0.y, r1.y);
            __syncthreads();
        }
    }

    #pragma unroll
    for (int mf = 0; mf < 2; mf++) {
        #pragma unroll
        for (int nf = 0; nf < 4; nf++) {
            int col = wn + nf * 8 + tig * 2;
            int gm0 = m0 + wm + mf * 16 + gid;
            int gm1 = gm0 + 8;
            if (gm0 < NN)
                *(__half2*)&T[((size_t)r * NN + gm0) * HH + col] =
                    __floats2half2_rn(acc[mf][nf][0], acc[mf][nf][1]);
            if (gm1 < NN)
                *(__half2*)&T[((size_t)r * NN + gm1) * HH + col] =
                    __floats2half2_rn(acc[mf][nf][2], acc[mf][nf][3]);
        }
    }
}

// ---------------- GEMM dual (fp16 mma, double-buffered, mu & lv): Tc interleaved ----------------
__global__ __launch_bounds__(256) void k_gemm2(const float* __restrict__ X,
                                               const float* __restrict__ Wa,
                                               const float* __restrict__ Wb,
                                               __half* __restrict__ Tc) {
    const int r  = blockIdx.y;
    const int m0 = blockIdx.x * BM;
    __shared__ unsigned As[2][BM][12];
    __shared__ unsigned Bs[2][2][8][HH + 8];
    const int tid  = threadIdx.x;
    const int warp = tid >> 5, lane = tid & 31;
    const int wm = (warp & 3) * 32;
    const int wn = (warp >> 2) * 32;
    const int gid = lane >> 2, tig = lane & 3;
    float acc[2][2][4][4] = {};
    const float* WrA = Wa + (size_t)r * HH * HH;
    const float* WrB = Wb + (size_t)r * HH * HH;

    const int a_row  = tid >> 1;
    const int a_half = tid & 1;
    const int b_kp   = tid >> 5;
    const int b_n    = (tid & 31) * 2;
    const int gm_a   = m0 + a_row;
    const int nk = HH / BK;

    float4 va0, va1;
    float2 ra0, ra1, rb0, rb1;
    {
        if (gm_a < NN) {
            const float* p = X + (size_t)gm_a * HH + a_half * 8;
            va0 = *(const float4*)p; va1 = *(const float4*)(p + 4);
        } else { va0 = make_float4(0.f,0.f,0.f,0.f); va1 = va0; }
        size_t o0 = (size_t)(2 * b_kp) * HH + b_n;
        size_t o1 = (size_t)(2 * b_kp + 1) * HH + b_n;
        ra0 = *(const float2*)(WrA + o0); ra1 = *(const float2*)(WrA + o1);
        rb0 = *(const float2*)(WrB + o0); rb1 = *(const float2*)(WrB + o1);
    }
    {
        unsigned* ap = &As[0][a_row][a_half * 4];
        ap[0] = packh2(va0.x, va0.y); ap[1] = packh2(va0.z, va0.w);
        ap[2] = packh2(va1.x, va1.y); ap[3] = packh2(va1.z, va1.w);
        Bs[0][0][b_kp][b_n]     = packh2(ra0.x, ra1.x);
        Bs[0][0][b_kp][b_n + 1] = packh2(ra0.y, ra1.y);
        Bs[0][1][b_kp][b_n]     = packh2(rb0.x, rb1.x);
        Bs[0][1][b_kp][b_n + 1] = packh2(rb0.y, rb1.y);
    }
    __syncthreads();

    for (int kt = 0; kt < nk; kt++) {
        const int cur = kt & 1;
        if (kt + 1 < nk) {
            int k0 = (kt + 1) * BK;
            if (gm_a < NN) {
                const float* p = X + (size_t)gm_a * HH + k0 + a_half * 8;
                va0 = *(const float4*)p; va1 = *(const float4*)(p + 4);
            } else { va0 = make_float4(0.f,0.f,0.f,0.f); va1 = va0; }
            size_t o0 = (size_t)(k0 + 2 * b_kp) * HH + b_n;
            size_t o1 = (size_t)(k0 + 2 * b_kp + 1) * HH + b_n;
            ra0 = *(const float2*)(WrA + o0); ra1 = *(const float2*)(WrA + o1);
            rb0 = *(const float2*)(WrB + o0); rb1 = *(const float2*)(WrB + o1);
        }
        {
            unsigned a[2][4];
            #pragma unroll
            for (int mf = 0; mf < 2; mf++) {
                int mr = wm + mf * 16;
                a[mf][0] = As[cur][mr + gid    ][tig];
                a[mf][1] = As[cur][mr + gid + 8][tig];
                a[mf][2] = As[cur][mr + gid    ][tig + 4];
                a[mf][3] = As[cur][mr + gid + 8][tig + 4];
            }
            #pragma unroll
            for (int s = 0; s < 2; s++) {
                unsigned b[4][2];
                #pragma unroll
                for (int nf = 0; nf < 4; nf++) {
                    int nc = wn + nf * 8;
                    b[nf][0] = Bs[cur][s][tig    ][nc + gid];
                    b[nf][1] = Bs[cur][s][tig + 4][nc + gid];
                }
                #pragma unroll
                for (int mf = 0; mf < 2; mf++)
                    #pragma unroll
                    for (int nf = 0; nf < 4; nf++)
                        mma_fp16(acc[s][mf][nf], a[mf], b[nf]);
            }
        }
        if (kt + 1 < nk) {
            const int nxt = (kt + 1) & 1;
            unsigned* ap = &As[nxt][a_row][a_half * 4];
            ap[0] = packh2(va0.x, va0.y); ap[1] = packh2(va0.z, va0.w);
            ap[2] = packh2(va1.x, va1.y); ap[3] = packh2(va1.z, va1.w);
            Bs[nxt][0][b_kp][b_n]     = packh2(ra0.x, ra1.x);
            Bs[nxt][0][b_kp][b_n + 1] = packh2(ra0.y, ra1.y);
            Bs[nxt][1][b_kp][b_n]     = packh2(rb0.x, rb1.x);
            Bs[nxt][1][b_kp][b_n + 1] = packh2(rb0.y, rb1.y);
            __syncthreads();
        }
    }

    #pragma unroll
    for (int s = 0; s < 2; s++) {
        #pragma unroll
        for (int mf = 0; mf < 2; mf++) {
            #pragma unroll
            for (int nf = 0; nf < 4; nf++) {
                int col = wn + nf * 8 + tig * 2;
                int p   = col >> 1;
                int gm0 = m0 + wm + mf * 16 + gid;
                int gm1 = gm0 + 8;
                if (gm0 < NN)
                    *(__half2*)&Tc[((size_t)(r * NN + gm0)) * 128 + 4 * p + 2 * s] =
                        __floats2half2_rn(acc[s][mf][nf][0], acc[s][mf][nf][1]);
                if (gm1 < NN)
                    *(__half2*)&Tc[((size_t)(r * NN + gm1)) * 128 + 4 * p + 2 * s] =
                        __floats2half2_rn(acc[s][mf][nf][2], acc[s][mf][nf][3]);
            }
        }
    }
}

// ---------------- per-node attention scalars (layer 1, set 0) ----------------
__global__ __launch_bounds__(256) void k_qdkd(const float* __restrict__ X, int Din) {
    __shared__ float swq[RR * DIN1], swk[RR * DIN1];
    int nb = RR * Din;
    for (int i = threadIdx.x; i < nb; i += 256) { swq[i] = g_wq[i]; swk[i] = g_wk[i]; }
    __syncthreads();
    int warp = threadIdx.x >> 5, lane = threadIdx.x & 31;
    int n = blockIdx.x * 8 + warp;
    if (n >= NN) return;
    float xv[4];
    int L = Din >> 5;
    #pragma unroll
    for (int l = 0; l < 4; l++)
        xv[l] = (l < L) ? X[(size_t)n * Din + lane + 32 * l] : 0.f;
    #pragma unroll
    for (int r = 0; r < RR; r++) {
        float aq = 0.f, ak = 0.f;
        #pragma unroll
        for (int l = 0; l < 4; l++) {
            if (l < L) {
                aq = fmaf(xv[l], swq[r * Din + lane + 32 * l], aq);
                ak = fmaf(xv[l], swk[r * Din + lane + 32 * l], ak);
            }
        }
        #pragma unroll
        for (int o = 16; o; o >>= 1) {
            aq += __shfl_down_sync(FULLMASK, aq, o);
            ak += __shfl_down_sync(FULLMASK, ak, o);
        }
        if (lane == 0) { g_qd[r * NN + n] = aq; g_kd[r * NN + n] = ak; }
    }
}

// ---------------- per-node attention scalars (mu set 1 & lv set 2, Din=HH) ----------------
__global__ __launch_bounds__(256) void k_qdkd2(const float* __restrict__ X) {
    __shared__ float swq[2][RR * HH], swk[2][RR * HH];
    for (int i = threadIdx.x; i < RR * HH; i += 256) {
        swq[0][i] = g_wq[RR * DIN1 + i];        swk[0][i] = g_wk[RR * DIN1 + i];
        swq[1][i] = g_wq[2 * RR * DIN1 + i];    swk[1][i] = g_wk[2 * RR * DIN1 + i];
    }
    __syncthreads();
    int warp = threadIdx.x >> 5, lane = threadIdx.x & 31;
    int n = blockIdx.x * 8 + warp;
    if (n >= NN) return;
    float x0 = X[(size_t)n * HH + lane];
    float x1 = X[(size_t)n * HH + lane + 32];
    #pragma unroll
    for (int r = 0; r < RR; r++) {
        float aq0 = x0 * swq[0][r * HH + lane] + x1 * swq[0][r * HH + lane + 32];
        float ak0 = x0 * swk[0][r * HH + lane] + x1 * swk[0][r * HH + lane + 32];
        float aq1 = x0 * swq[1][r * HH + lane] + x1 * swq[1][r * HH + lane + 32];
        float ak1 = x0 * swk[1][r * HH + lane] + x1 * swk[1][r * HH + lane + 32];
        #pragma unroll
        for (int o = 16; o; o >>= 1) {
            aq0 += __shfl_down_sync(FULLMASK, aq0, o);
            ak0 += __shfl_down_sync(FULLMASK, ak0, o);
            aq1 += __shfl_down_sync(FULLMASK, aq1, o);
            ak1 += __shfl_down_sync(FULLMASK, ak1, o);
        }
        if (lane == 0) {
            g_qd[r * NN + n] = aq0;
            g_qd[RR * NN + r * NN + n] = aq1;
            g_kd2[r * NN + n] = make_float2(ak0, ak1);
        }
    }
}

// ---------------- fused softmax + aggregation (layer 1); 4 edges per j-iter ----------------
__global__ __launch_bounds__(256) void k_agg(const __half* __restrict__ T,
                                             const float* __restrict__ bias,
                                             float* __restrict__ outfeat) {
    __shared__ int   s_ro[8][32];
    __shared__ float s_ex[8][32];
    int warp = threadIdx.x >> 5, lane = threadIdx.x & 31;
    int n = blockIdx.x * 8 + warp;
    if (n >= NN) return;
    int s0 = g_off[n], s1e = g_off[n + 1];
    float qv = (lane < RR) ? g_qd[lane * NN + n] : 0.f;
    const int sub = lane >> 3;
    const int c   = lane & 7;
    float acc[8] = {};
    float ssum = 0.f;
    for (int base = s0; base < s1e; base += 32) {
        int m = s1e - base; if (m > 32) m = 32;
        bool valid = (base + lane) < s1e;
        unsigned u = valid ? g_edges[base + lane] : 0u;
        int srcL = (int)(u & 0xFFFFu), etL = (int)(u >> 16);
        int ro = etL * NN + srcL;
        float a = __shfl_sync(FULLMASK, qv, etL) + __ldg(&g_kd[ro]);
        a = (a >= 0.f) ? a : 0.2f * a;
        float ex = valid ? __expf(a) : 0.f;
        ssum += ex;
        s_ro[warp][lane] = valid ? ro : 0;
        s_ex[warp][lane] = ex;
        __syncwarp();
        int mp = (m + 3) >> 2;
        #pragma unroll 4
        for (int j = 0; j < mp; j++) {
            int j2 = 4 * j + sub;
            int   roj = s_ro[warp][j2];
            float exj = s_ex[warp][j2];
            uint4 pk = *(const uint4*)(T + (size_t)roj * HH + 8 * c);
            float2 t0 = __half22float2(*(const __half2*)&pk.x);
            float2 t1 = __half22float2(*(const __half2*)&pk.y);
            float2 t2 = __half22float2(*(const __half2*)&pk.z);
            float2 t3 = __half22float2(*(const __half2*)&pk.w);
            acc[0] = fmaf(exj, t0.x, acc[0]); acc[1] = fmaf(exj, t0.y, acc[1]);
            acc[2] = fmaf(exj, t1.x, acc[2]); acc[3] = fmaf(exj, t1.y, acc[3]);
            acc[4] = fmaf(exj, t2.x, acc[4]); acc[5] = fmaf(exj, t2.y, acc[5]);
            acc[6] = fmaf(exj, t3.x, acc[6]); acc[7] = fmaf(exj, t3.y, acc[7]);
        }
        __syncwarp();
    }
    #pragma unroll
    for (int i = 0; i < 8; i++) {
        acc[i] += __shfl_xor_sync(FULLMASK, acc[i], 8);
        acc[i] += __shfl_xor_sync(FULLMASK, acc[i], 16);
    }
    #pragma unroll
    for (int o = 16; o; o >>= 1) ssum += __shfl_xor_sync(FULLMASK, ssum, o);
    float inv = 1.0f / (ssum + 1e-16f);
    if (sub == 0) {
        float4 bv0 = *(const float4*)(bias + 8 * c);
        float4 bv1 = *(const float4*)(bias + 8 * c + 4);
        float4 o0, o1;
        o0.x = fmaxf(acc[0] * inv + bv0.x, 0.f);
        o0.y = fmaxf(acc[1] * inv + bv0.y, 0.f);
        o0.z = fmaxf(acc[2] * inv + bv0.z, 0.f);
        o0.w = fmaxf(acc[3] * inv + bv0.w, 0.f);
        o1.x = fmaxf(acc[4] * inv + bv1.x, 0.f);
        o1.y = fmaxf(acc[5] * inv + bv1.y, 0.f);
        o1.z = fmaxf(acc[6] * inv + bv1.z, 0.f);
        o1.w = fmaxf(acc[7] * inv + bv1.w, 0.f);
        *(float4*)(outfeat + (size_t)n * HH + 8 * c)     = o0;
        *(float4*)(outfeat + (size_t)n * HH + 8 * c + 4) = o1;
    }
}

// ---------------- fused softmax + aggregation (mu & lv) + output linears ----------------
__global__ __launch_bounds__(256) void k_agg2(const __half* __restrict__ Tc,
                                              const float* __restrict__ bias_a,
                                              const float* __restrict__ bias_b,
                                              const float* __restrict__ Wm,
                                              const float* __restrict__ bm,
                                              const float* __restrict__ Wl,
                                              const float* __restrict__ bl,
                                              float* __restrict__ out) {
    __shared__ int   s_ro[8][32];
    __shared__ float s_ea[8][32];
    __shared__ float s_eb[8][32];
    __shared__ float s_rm[8][HH];
    __shared__ float s_rl[8][HH];
    __shared__ float sWm[HH * OUTD];
    __shared__ float sWl[HH * OUTD];
    int tid = threadIdx.x;
    for (int i = tid; i < HH * OUTD; i += 256) { sWm[i] = Wm[i]; sWl[i] = Wl[i]; }
    __syncthreads();

    int warp = tid >> 5, lane = tid & 31;
    int n = blockIdx.x * 8 + warp;
    if (n >= NN) return;
    int s0 = g_off[n], s1e = g_off[n + 1];
    float qva = (lane < RR) ? g_qd[lane * NN + n] : 0.f;
    float qvb = (lane < RR) ? g_qd[RR * NN + lane * NN + n] : 0.f;
    const int h = lane >> 4, c = lane & 15;
    float a0 = 0.f, a1 = 0.f, a2 = 0.f, a3 = 0.f, sa = 0.f;
    float b0 = 0.f, b1 = 0.f, b2 = 0.f, b3 = 0.f, sb = 0.f;
    for (int base = s0; base < s1e; base += 32) {
        int m = s1e - base; if (m > 32) m = 32;
        bool valid = (base + lane) < s1e;
        unsigned u = valid ? g_edges[base + lane] : 0u;
        int srcL = (int)(u & 0xFFFFu), etL = (int)(u >> 16);
        int ro = etL * NN + srcL;
        float2 kk = __ldg(&g_kd2[ro]);
        float la = __shfl_sync(FULLMASK, qva, etL) + kk.x;
        float lb = __shfl_sync(FULLMASK, qvb, etL) + kk.y;
        la = (la >= 0.f) ? la : 0.2f * la;
        lb = (lb >= 0.f) ? lb : 0.2f * lb;
        float exa = valid ? __expf(la) : 0.f;
        float exb = valid ? __expf(lb) : 0.f;
        sa += exa; sb += exb;
        s_ro[warp][lane] = valid ? ro : 0;
        s_ea[warp][lane] = exa;
        s_eb[warp][lane] = exb;
        __syncwarp();
        int mp = (m + 1) >> 1;
        #pragma unroll 8
        for (int j = 0; j < mp; j++) {
            int j2 = 2 * j + h;
            int   roj = s_ro[warp][j2];
            float ea  = s_ea[warp][j2];
            float eb  = s_eb[warp][j2];
            uint4 pk = *(const uint4*)(Tc + (size_t)roj * 128 + 8 * c);
            float2 ta0 = __half22float2(*(const __half2*)&pk.x);
            float2 tb0 = __half22float2(*(const __half2*)&pk.y);
            float2 ta1 = __half22float2(*(const __half2*)&pk.z);
            float2 tb1 = __half22float2(*(const __half2*)&pk.w);
            a0 = fmaf(ea, ta0.x, a0); a1 = fmaf(ea, ta0.y, a1);
            a2 = fmaf(ea, ta1.x, a2); a3 = fmaf(ea, ta1.y, a3);
            b0 = fmaf(eb, tb0.x, b0); b1 = fmaf(eb, tb0.y, b1);
            b2 = fmaf(eb, tb1.x, b2); b3 = fmaf(eb, tb1.y, b3);
        }
        __syncwarp();
    }
    a0 += __shfl_xor_sync(FULLMASK, a0, 16);
    a1 += __shfl_xor_sync(FULLMASK, a1, 16);
    a2 += __shfl_xor_sync(FULLMASK, a2, 16);
    a3 += __shfl_xor_sync(FULLMASK, a3, 16);
    b0 += __shfl_xor_sync(FULLMASK, b0, 16);
    b1 += __shfl_xor_sync(FULLMASK, b1, 16);
    b2 += __shfl_xor_sync(FULLMASK, b2, 16);
    b3 += __shfl_xor_sync(FULLMASK, b3, 16);
    #pragma unroll
    for (int o = 16; o; o >>= 1) {
        sa += __shfl_xor_sync(FULLMASK, sa, o);
        sb += __shfl_xor_sync(FULLMASK, sb, o);
    }
    float ia = 1.0f / (sa + 1e-16f);
    float ib = 1.0f / (sb + 1e-16f);
    if (h == 0) {
        float4 bva = *(const float4*)(bias_a + 4 * c);
        float4 bvb = *(const float4*)(bias_b + 4 * c);
        float4 oa, ob;
        oa.x = fmaxf(a0 * ia + bva.x, 0.f);
        oa.y = fmaxf(a1 * ia + bva.y, 0.f);
        oa.z = fmaxf(a2 * ia + bva.z, 0.f);
        oa.w = fmaxf(a3 * ia + bva.w, 0.f);
        ob.x = fmaxf(b0 * ib + bvb.x, 0.f);
        ob.y = fmaxf(b1 * ib + bvb.y, 0.f);
        ob.z = fmaxf(b2 * ib + bvb.z, 0.f);
        ob.w = fmaxf(b3 * ib + bvb.w, 0.f);
        *(float4*)&s_rm[warp][4 * c] = oa;
        *(float4*)&s_rl[warp][4 * c] = ob;
    }
    __syncwarp();
    float am = 0.f, al = 0.f;
    #pragma unroll 8
    for (int k = 0; k < HH; k++) {
        float rm = s_rm[warp][k];
        float rl = s_rl[warp][k];
        am = fmaf(rm, sWm[k * OUTD + lane], am);
        al = fmaf(rl, sWl[k * OUTD + lane], al);
    }
    out[(size_t)n * OUTD + lane] = am + __ldg(&bm[lane]);
    out[(size_t)NN * OUTD + (size_t)n * OUTD + lane] = 0.5f * (al + __ldg(&bl[lane]));
}

// ---------------- launch ----------------
extern "C" void kernel_launch(void* const* d_in, const int* in_sizes, int n_in,
                              void* d_out, int out_size) {
    const float* x   = (const float*)d_in[0];
    const int*   ei  = (const int*)d_in[1];
    const int*   et  = (const int*)d_in[2];
    const float* W1  = (const float*)d_in[3];
    const float* q1  = (const float*)d_in[4];
    const float* k1  = (const float*)d_in[5];
    const float* b1  = (const float*)d_in[6];
    const float* Wmu = (const float*)d_in[7];
    const float* qmu = (const float*)d_in[8];
    const float* kmu = (const float*)d_in[9];
    const float* bmu = (const float*)d_in[10];
    const float* Wlv = (const float*)d_in[11];
    const float* qlv = (const float*)d_in[12];
    const float* klv = (const float*)d_in[13];
    const float* blv = (const float*)d_in[14];
    const float* Wm  = (const float*)d_in[15];
    const float* bm  = (const float*)d_in[16];
    const float* Wl  = (const float*)d_in[17];
    const float* bl  = (const float*)d_in[18];
    const int* src = ei;
    const int* dst = ei + EE;
    float* out = (float*)d_out;

    float*  hidden; cudaGetSymbolAddress((void**)&hidden, g_hidden);
    __half* ta;     cudaGetSymbolAddress((void**)&ta, g_ta);
    __half* tc;     cudaGetSymbolAddress((void**)&tc, g_tc);

    static cudaStream_t s1 = nullptr, s2 = nullptr;
    static cudaEvent_t evFork, evCSR, evHid, evQd2, evW1, evQd1;
    if (!s1) {
        cudaStreamCreateWithFlags(&s1, cudaStreamNonBlocking);
        cudaStreamCreateWithFlags(&s2, cudaStreamNonBlocking);
        cudaEventCreateWithFlags(&evFork, cudaEventDisableTiming);
        cudaEventCreateWithFlags(&evCSR,  cudaEventDisableTiming);
        cudaEventCreateWithFlags(&evHid,  cudaEventDisableTiming);
        cudaEventCreateWithFlags(&evQd2,  cudaEventDisableTiming);
        cudaEventCreateWithFlags(&evW1,   cudaEventDisableTiming);
        cudaEventCreateWithFlags(&evQd1,  cudaEventDisableTiming);
    }

    const int TB = 256;
    dim3 gemm_grid((NN + BM - 1) / BM, RR);
    int node_warp_blocks = (NN + 7) / 8;

    // ---- submission order chosen so the profiler's capture slot (4th launch)
    //      lands on k_gemm; execution dependencies are identical to R13 ----
    cudaEventRecord(evFork, 0);
    cudaStreamWaitEvent(s1, evFork, 0);
    k_zero_off<<<(NN + 1 + TB - 1) / TB, TB, 0, s1>>>();            // L1
    k_wqwk3<<<3, TB>>>(W1, q1, k1, Wmu, qmu, kmu, Wlv, qlv, klv);   // L2 (stream 0)
    cudaEventRecord(evW1, 0);
    cudaStreamWaitEvent(s2, evW1, 0);
    k_qdkd<<<node_warp_blocks, TB, 0, s2>>>(x, DIN1);               // L3
    cudaEventRecord(evQd1, s2);
    k_gemm<<<gemm_grid, TB>>>(x, W1, ta, DIN1);                     // L4  <- ncu slot
    k_hist<<<EE / TB, TB, 0, s1>>>(dst);                            // L5
    k_scan<<<1, 1024, 0, s1>>>();                                   // L6
    k_scatter<<<EE / TB, TB, 0, s1>>>(src, dst, et);                // L7
    cudaEventRecord(evCSR, s1);

    cudaStreamWaitEvent(0, evCSR, 0);
    cudaStreamWaitEvent(0, evQd1, 0);
    k_agg<<<node_warp_blocks, TB>>>(ta, b1, hidden);                // L8
    cudaEventRecord(evHid, 0);

    cudaStreamWaitEvent(s1, evHid, 0);
    k_qdkd2<<<node_warp_blocks, TB, 0, s1>>>(hidden);               // L9
    cudaEventRecord(evQd2, s1);

    k_gemm2<<<gemm_grid, TB>>>(hidden, Wmu, Wlv, tc);               // L10
    cudaStreamWaitEvent(0, evQd2, 0);
    k_agg2<<<node_warp_blocks, TB>>>(tc, bmu, blv, Wm, bm, Wl, bl, out);  // L11
    // duplicate launch: differential timing of a warm agg2 (same output, WAW-ordered)
    k_agg2<<<node_warp_blocks, TB>>>(tc, bmu, blv, Wm, bm, Wl, bl, out);  // L12
}

// round 15
// speedup vs baseline: 1.2365x; 1.2365x over previous
#include <cuda_runtime.h>
#include <cuda_fp16.h>
#include <cstdint>

#define NN 50000
#define EE 1600000
#define RR 8
#define DIN1 128
#define HH 64
#define OUTD 32
#define FULLMASK 0xffffffffu

// ---------------- scratch (static device globals; allocation-free) ----------------
__device__ __half   g_ta[(size_t)RR * NN * HH];        // layer-1 transformed feats (fp16)
__device__ __half   g_tc[(size_t)RR * NN * 2 * HH];    // mu/lv interleaved: row=128 halves
__device__ float    g_qd[2 * RR * NN];
__device__ float    g_kd[RR * NN];                     // layer-1 kd
__device__ float2   g_kd2[RR * NN];                    // (kd_mu, kd_lv)
__device__ float    g_wq[3 * RR * DIN1];               // set 0: layer1, 1: mu, 2: lv
__device__ float    g_wk[3 * RR * DIN1];
__device__ float    g_hidden[NN * HH];
__device__ int      g_off[NN + 1];
__device__ int      g_cursor[NN];
__device__ unsigned g_edges[EE];                       // src | (etype<<16)

// ---------------- CSR build ----------------
__global__ void k_zero_off() {
    int i = blockIdx.x * blockDim.x + threadIdx.x;
    if (i <= NN) g_off[i] = 0;
}

__global__ void k_hist(const int* __restrict__ dst) {
    int e = blockIdx.x * blockDim.x + threadIdx.x;
    if (e < EE) atomicAdd(&g_off[dst[e]], 1);
}

__global__ void k_scan() {
    __shared__ int wsum[32];
    const int tid = threadIdx.x, lane = tid & 31, wid = tid >> 5;
    int carry = 0;
    for (int base = 0; base < NN; base += 1024) {
        int i = base + tid;
        int v = (i < NN) ? g_off[i] : 0;
        int s = v;
        #pragma unroll
        for (int o = 1; o < 32; o <<= 1) {
            int t = __shfl_up_sync(FULLMASK, s, o);
            if (lane >= o) s += t;
        }
        if (lane == 31) wsum[wid] = s;
        __syncthreads();
        if (wid == 0) {
            int ws = wsum[lane];
            #pragma unroll
            for (int o = 1; o < 32; o <<= 1) {
                int t = __shfl_up_sync(FULLMASK, ws, o);
                if (lane >= o) ws += t;
            }
            wsum[lane] = ws;
        }
        __syncthreads();
        int excl = s - v + (wid ? wsum[wid - 1] : 0) + carry;
        if (i < NN) { g_off[i] = excl; g_cursor[i] = excl; }
        int total = wsum[31];
        __syncthreads();
        carry += total;
    }
    if (tid == 0) g_off[NN] = carry;
}

__global__ void k_scatter(const int* __restrict__ src, const int* __restrict__ dst,
                          const int* __restrict__ et) {
    int e = blockIdx.x * blockDim.x + threadIdx.x;
    if (e < EE) {
        int pos = atomicAdd(&g_cursor[dst[e]], 1);
        g_edges[pos] = (unsigned)src[e] | ((unsigned)et[e] << 16);
    }
}

// ---------------- all three wq/wk sets in one kernel (blockIdx.x = set) ----------------
__global__ void k_wqwk3(const float* __restrict__ W1, const float* __restrict__ q1,
                        const float* __restrict__ k1,
                        const float* __restrict__ Wmu, const float* __restrict__ qmu,
                        const float* __restrict__ kmu,
                        const float* __restrict__ Wlv, const float* __restrict__ qlv,
                        const float* __restrict__ klv) {
    const int set = blockIdx.x;
    const float* W = (set == 0) ? W1 : (set == 1) ? Wmu : Wlv;
    const float* q = (set == 0) ? q1 : (set == 1) ? qmu : qlv;
    const float* k = (set == 0) ? k1 : (set == 1) ? kmu : klv;
    const int Din = (set == 0) ? DIN1 : HH;
    __shared__ float qs[HH], ks[HH];
    if (threadIdx.x < HH) { qs[threadIdx.x] = q[threadIdx.x]; ks[threadIdx.x] = k[threadIdx.x]; }
    __syncthreads();
    for (int e = threadIdx.x; e < RR * Din; e += blockDim.x) {
        const float* w = W + (size_t)e * HH;
        float aq = 0.f, ak = 0.f;
        #pragma unroll 8
        for (int o = 0; o < HH; o++) { float wv = w[o]; aq += wv * qs[o]; ak += wv * ks[o]; }
        g_wq[set * RR * DIN1 + e] = aq;
        g_wk[set * RR * DIN1 + e] = ak;
    }
}

// ---------------- fp16 mma helpers ----------------
__device__ __forceinline__ unsigned packh2(float a, float b) {
    __half2 h = __floats2half2_rn(a, b);
    return *(unsigned*)&h;
}

__device__ __forceinline__ void mma_fp16(float* d, const unsigned* a, const unsigned* b) {
    asm volatile(
        "mma.sync.aligned.m16n8k16.row.col.f32.f16.f16.f32 "
        "{%0,%1,%2,%3}, {%4,%5,%6,%7}, {%8,%9}, {%0,%1,%2,%3};\n"
        : "+f"(d[0]), "+f"(d[1]), "+f"(d[2]), "+f"(d[3])
        : "r"(a[0]), "r"(a[1]), "r"(a[2]), "r"(a[3]), "r"(b[0]), "r"(b[1]));
}

__device__ __forceinline__ void ldsm_x4(unsigned* r, uint32_t addr) {
    asm volatile("ldmatrix.sync.aligned.m8n8.x4.shared.b16 {%0,%1,%2,%3}, [%4];"
                 : "=r"(r[0]), "=r"(r[1]), "=r"(r[2]), "=r"(r[3]) : "r"(addr));
}

// ---------------- GEMM layer 1 (fp16 mma + ldmatrix A, double-buffered) ----------------
#define BM 128
#define BK 16
__global__ __launch_bounds__(256) void k_gemm(const float* __restrict__ X,
                                              const float* __restrict__ W,
                                              __half* __restrict__ T, int Din) {
    const int r  = blockIdx.y;
    const int m0 = blockIdx.x * BM;
    __shared__ unsigned As[2][BM][12];
    __shared__ unsigned Bs[2][8][HH + 8];
    const int tid  = threadIdx.x;
    const int warp = tid >> 5, lane = tid & 31;
    const int wm = (warp & 3) * 32;
    const int wn = (warp >> 2) * 32;
    const int gid = lane >> 2, tig = lane & 3;
    float acc[2][4][4] = {};
    const float* Wr = W + (size_t)r * Din * HH;

    const int a_row  = tid >> 1;
    const int a_half = tid & 1;
    const int b_kp   = tid >> 5;
    const int b_n    = (tid & 31) * 2;
    const int gm_a   = m0 + a_row;
    const int nk = Din / BK;

    // ldmatrix per-lane source: quad 0/1 -> rows +0/+8 k0-7; quad 2/3 -> rows +0/+8 k8-15
    const int lrow = (lane & 7) + ((lane >> 3) & 1) * 8;
    const int lcol = (lane >> 4) * 4;                  // unsigned units
    const uint32_t a_base = (uint32_t)__cvta_generic_to_shared(&As[0][0][0]);

    float4 va0, va1;
    float2 r0, r1;
    {
        if (gm_a < NN) {
            const float* p = X + (size_t)gm_a * Din + a_half * 8;
            va0 = *(const float4*)p; va1 = *(const float4*)(p + 4);
        } else { va0 = make_float4(0.f,0.f,0.f,0.f); va1 = va0; }
        r0 = *(const float2*)(Wr + (size_t)(2 * b_kp)     * HH + b_n);
        r1 = *(const float2*)(Wr + (size_t)(2 * b_kp + 1) * HH + b_n);
    }
    {
        unsigned* ap = &As[0][a_row][a_half * 4];
        ap[0] = packh2(va0.x, va0.y); ap[1] = packh2(va0.z, va0.w);
        ap[2] = packh2(va1.x, va1.y); ap[3] = packh2(va1.z, va1.w);
        Bs[0][b_kp][b_n]     = packh2(r0.x, r1.x);
        Bs[0][b_kp][b_n + 1] = packh2(r0.y, r1.y);
    }
    __syncthreads();

    for (int kt = 0; kt < nk; kt++) {
        const int cur = kt & 1;
        if (kt + 1 < nk) {
            int k0 = (kt + 1) * BK;
            if (gm_a < NN) {
                const float* p = X + (size_t)gm_a * Din + k0 + a_half * 8;
                va0 = *(const float4*)p; va1 = *(const float4*)(p + 4);
            } else { va0 = make_float4(0.f,0.f,0.f,0.f); va1 = va0; }
            r0 = *(const float2*)(Wr + (size_t)(k0 + 2 * b_kp)     * HH + b_n);
            r1 = *(const float2*)(Wr + (size_t)(k0 + 2 * b_kp + 1) * HH + b_n);
        }
        {
            unsigned a[2][4], b[4][2];
            #pragma unroll
            for (int mf = 0; mf < 2; mf++) {
                int mr = wm + mf * 16;
                uint32_t addr = a_base + ((uint32_t)((cur * BM + mr + lrow) * 12 + lcol) << 2);
                ldsm_x4(a[mf], addr);
            }
            #pragma unroll
            for (int nf = 0; nf < 4; nf++) {
                int nc = wn + nf * 8;
                b[nf][0] = Bs[cur][tig    ][nc + gid];
                b[nf][1] = Bs[cur][tig + 4][nc + gid];
            }
            #pragma unroll
            for (int mf = 0; mf < 2; mf++)
                #pragma unroll
                for (int nf = 0; nf < 4; nf++)
                    mma_fp16(acc[mf][nf], a[mf], b[nf]);
        }
        if (kt + 1 < nk) {
            const int nxt = (kt + 1) & 1;
            unsigned* ap = &As[nxt][a_row][a_half * 4];
            ap[0] = packh2(va0.x, va0.y); ap[1] = packh2(va0.z, va0.w);
            ap[2] = packh2(va1.x, va1.y); ap[3] = packh2(va1.z, va1.w);
            Bs[nxt][b_kp][b_n]     = packh2(r0.x, r1.x);
            Bs[nxt][b_kp][b_n + 1] = packh2(r0.y, r1.y);
            __syncthreads();
        }
    }

    #pragma unroll
    for (int mf = 0; mf < 2; mf++) {
        #pragma unroll
        for (int nf = 0; nf < 4; nf++) {
            int col = wn + nf * 8 + tig * 2;
            int gm0 = m0 + wm + mf * 16 + gid;
            int gm1 = gm0 + 8;
            if (gm0 < NN)
                *(__half2*)&T[((size_t)r * NN + gm0) * HH + col] =
                    __floats2half2_rn(acc[mf][nf][0], acc[mf][nf][1]);
            if (gm1 < NN)
                *(__half2*)&T[((size_t)r * NN + gm1) * HH + col] =
                    __floats2half2_rn(acc[mf][nf][2], acc[mf][nf][3]);
        }
    }
}

// ---------------- GEMM dual (fp16 mma + ldmatrix A, mu & lv): Tc interleaved ----------------
__global__ __launch_bounds__(256) void k_gemm2(const float* __restrict__ X,
                                               const float* __restrict__ Wa,
                                               const float* __restrict__ Wb,
                                               __half* __restrict__ Tc) {
    const int r  = blockIdx.y;
    const int m0 = blockIdx.x * BM;
    __shared__ unsigned As[2][BM][12];
    __shared__ unsigned Bs[2][2][8][HH + 8];
    const int tid  = threadIdx.x;
    const int warp = tid >> 5, lane = tid & 31;
    const int wm = (warp & 3) * 32;
    const int wn = (warp >> 2) * 32;
    const int gid = lane >> 2, tig = lane & 3;
    float acc[2][2][4][4] = {};
    const float* WrA = Wa + (size_t)r * HH * HH;
    const float* WrB = Wb + (size_t)r * HH * HH;

    const int a_row  = tid >> 1;
    const int a_half = tid & 1;
    const int b_kp   = tid >> 5;
    const int b_n    = (tid & 31) * 2;
    const int gm_a   = m0 + a_row;
    const int nk = HH / BK;

    const int lrow = (lane & 7) + ((lane >> 3) & 1) * 8;
    const int lcol = (lane >> 4) * 4;
    const uint32_t a_base = (uint32_t)__cvta_generic_to_shared(&As[0][0][0]);

    float4 va0, va1;
    float2 ra0, ra1, rb0, rb1;
    {
        if (gm_a < NN) {
            const float* p = X + (size_t)gm_a * HH + a_half * 8;
            va0 = *(const float4*)p; va1 = *(const float4*)(p + 4);
        } else { va0 = make_float4(0.f,0.f,0.f,0.f); va1 = va0; }
        size_t o0 = (size_t)(2 * b_kp) * HH + b_n;
        size_t o1 = (size_t)(2 * b_kp + 1) * HH + b_n;
        ra0 = *(const float2*)(WrA + o0); ra1 = *(const float2*)(WrA + o1);
        rb0 = *(const float2*)(WrB + o0); rb1 = *(const float2*)(WrB + o1);
    }
    {
        unsigned* ap = &As[0][a_row][a_half * 4];
        ap[0] = packh2(va0.x, va0.y); ap[1] = packh2(va0.z, va0.w);
        ap[2] = packh2(va1.x, va1.y); ap[3] = packh2(va1.z, va1.w);
        Bs[0][0][b_kp][b_n]     = packh2(ra0.x, ra1.x);
        Bs[0][0][b_kp][b_n + 1] = packh2(ra0.y, ra1.y);
        Bs[0][1][b_kp][b_n]     = packh2(rb0.x, rb1.x);
        Bs[0][1][b_kp][b_n + 1] = packh2(rb0.y, rb1.y);
    }
    __syncthreads();

    for (int kt = 0; kt < nk; kt++) {
        const int cur = kt & 1;
        if (kt + 1 < nk) {
            int k0 = (kt + 1) * BK;
            if (gm_a < NN) {
                const float* p = X + (size_t)gm_a * HH + k0 + a_half * 8;
                va0 = *(const float4*)p; va1 = *(const float4*)(p + 4);
            } else { va0 = make_float4(0.f,0.f,0.f,0.f); va1 = va0; }
            size_t o0 = (size_t)(k0 + 2 * b_kp) * HH + b_n;
            size_t o1 = (size_t)(k0 + 2 * b_kp + 1) * HH + b_n;
            ra0 = *(const float2*)(WrA + o0); ra1 = *(const float2*)(WrA + o1);
            rb0 = *(const float2*)(WrB + o0); rb1 = *(const float2*)(WrB + o1);
        }
        {
            unsigned a[2][4];
            #pragma unroll
            for (int mf = 0; mf < 2; mf++) {
                int mr = wm + mf * 16;
                uint32_t addr = a_base + ((uint32_t)((cur * BM + mr + lrow) * 12 + lcol) << 2);
                ldsm_x4(a[mf], addr);
            }
            #pragma unroll
            for (int s = 0; s < 2; s++) {
                unsigned b[4][2];
                #pragma unroll
                for (int nf = 0; nf < 4; nf++) {
                    int nc = wn + nf * 8;
                    b[nf][0] = Bs[cur][s][tig    ][nc + gid];
                    b[nf][1] = Bs[cur][s][tig + 4][nc + gid];
                }
                #pragma unroll
                for (int mf = 0; mf < 2; mf++)
                    #pragma unroll
                    for (int nf = 0; nf < 4; nf++)
                        mma_fp16(acc[s][mf][nf], a[mf], b[nf]);
            }
        }
        if (kt + 1 < nk) {
            const int nxt = (kt + 1) & 1;
            unsigned* ap = &As[nxt][a_row][a_half * 4];
            ap[0] = packh2(va0.x, va0.y); ap[1] = packh2(va0.z, va0.w);
            ap[2] = packh2(va1.x, va1.y); ap[3] = packh2(va1.z, va1.w);
            Bs[nxt][0][b_kp][b_n]     = packh2(ra0.x, ra1.x);
            Bs[nxt][0][b_kp][b_n + 1] = packh2(ra0.y, ra1.y);
            Bs[nxt][1][b_kp][b_n]     = packh2(rb0.x, rb1.x);
            Bs[nxt][1][b_kp][b_n + 1] = packh2(rb0.y, rb1.y);
            __syncthreads();
        }
    }

    #pragma unroll
    for (int s = 0; s < 2; s++) {
        #pragma unroll
        for (int mf = 0; mf < 2; mf++) {
            #pragma unroll
            for (int nf = 0; nf < 4; nf++) {
                int col = wn + nf * 8 + tig * 2;
                int p   = col >> 1;
                int gm0 = m0 + wm + mf * 16 + gid;
                int gm1 = gm0 + 8;
                if (gm0 < NN)
                    *(__half2*)&Tc[((size_t)(r * NN + gm0)) * 128 + 4 * p + 2 * s] =
                        __floats2half2_rn(acc[s][mf][nf][0], acc[s][mf][nf][1]);
                if (gm1 < NN)
                    *(__half2*)&Tc[((size_t)(r * NN + gm1)) * 128 + 4 * p + 2 * s] =
                        __floats2half2_rn(acc[s][mf][nf][2], acc[s][mf][nf][3]);
            }
        }
    }
}

// ---------------- per-node attention scalars (layer 1, set 0) ----------------
__global__ __launch_bounds__(256) void k_qdkd(const float* __restrict__ X, int Din) {
    __shared__ float swq[RR * DIN1], swk[RR * DIN1];
    int nb = RR * Din;
    for (int i = threadIdx.x; i < nb; i += 256) { swq[i] = g_wq[i]; swk[i] = g_wk[i]; }
    __syncthreads();
    int warp = threadIdx.x >> 5, lane = threadIdx.x & 31;
    int n = blockIdx.x * 8 + warp;
    if (n >= NN) return;
    float xv[4];
    int L = Din >> 5;
    #pragma unroll
    for (int l = 0; l < 4; l++)
        xv[l] = (l < L) ? X[(size_t)n * Din + lane + 32 * l] : 0.f;
    #pragma unroll
    for (int r = 0; r < RR; r++) {
        float aq = 0.f, ak = 0.f;
        #pragma unroll
        for (int l = 0; l < 4; l++) {
            if (l < L) {
                aq = fmaf(xv[l], swq[r * Din + lane + 32 * l], aq);
                ak = fmaf(xv[l], swk[r * Din + lane + 32 * l], ak);
            }
        }
        #pragma unroll
        for (int o = 16; o; o >>= 1) {
            aq += __shfl_down_sync(FULLMASK, aq, o);
            ak += __shfl_down_sync(FULLMASK, ak, o);
        }
        if (lane == 0) { g_qd[r * NN + n] = aq; g_kd[r * NN + n] = ak; }
    }
}

// ---------------- per-node attention scalars (mu set 1 & lv set 2, Din=HH) ----------------
__global__ __launch_bounds__(256) void k_qdkd2(const float* __restrict__ X) {
    __shared__ float swq[2][RR * HH], swk[2][RR * HH];
    for (int i = threadIdx.x; i < RR * HH; i += 256) {
        swq[0][i] = g_wq[RR * DIN1 + i];        swk[0][i] = g_wk[RR * DIN1 + i];
        swq[1][i] = g_wq[2 * RR * DIN1 + i];    swk[1][i] = g_wk[2 * RR * DIN1 + i];
    }
    __syncthreads();
    int warp = threadIdx.x >> 5, lane = threadIdx.x & 31;
    int n = blockIdx.x * 8 + warp;
    if (n >= NN) return;
    float x0 = X[(size_t)n * HH + lane];
    float x1 = X[(size_t)n * HH + lane + 32];
    #pragma unroll
    for (int r = 0; r < RR; r++) {
        float aq0 = x0 * swq[0][r * HH + lane] + x1 * swq[0][r * HH + lane + 32];
        float ak0 = x0 * swk[0][r * HH + lane] + x1 * swk[0][r * HH + lane + 32];
        float aq1 = x0 * swq[1][r * HH + lane] + x1 * swq[1][r * HH + lane + 32];
        float ak1 = x0 * swk[1][r * HH + lane] + x1 * swk[1][r * HH + lane + 32];
        #pragma unroll
        for (int o = 16; o; o >>= 1) {
            aq0 += __shfl_down_sync(FULLMASK, aq0, o);
            ak0 += __shfl_down_sync(FULLMASK, ak0, o);
            aq1 += __shfl_down_sync(FULLMASK, aq1, o);
            ak1 += __shfl_down_sync(FULLMASK, ak1, o);
        }
        if (lane == 0) {
            g_qd[r * NN + n] = aq0;
            g_qd[RR * NN + r * NN + n] = aq1;
            g_kd2[r * NN + n] = make_float2(ak0, ak1);
        }
    }
}

// ---------------- fused softmax + aggregation (layer 1); 4 edges per j-iter ----------------
__global__ __launch_bounds__(256) void k_agg(const __half* __restrict__ T,
                                             const float* __restrict__ bias,
                                             float* __restrict__ outfeat) {
    __shared__ int   s_ro[8][32];
    __shared__ float s_ex[8][32];
    int warp = threadIdx.x >> 5, lane = threadIdx.x & 31;
    int n = blockIdx.x * 8 + warp;
    if (n >= NN) return;
    int s0 = g_off[n], s1e = g_off[n + 1];
    float qv = (lane < RR) ? g_qd[lane * NN + n] : 0.f;
    const int sub = lane >> 3;
    const int c   = lane & 7;
    float acc[8] = {};
    float ssum = 0.f;
    for (int base = s0; base < s1e; base += 32) {
        int m = s1e - base; if (m > 32) m = 32;
        bool valid = (base + lane) < s1e;
        unsigned u = valid ? g_edges[base + lane] : 0u;
        int srcL = (int)(u & 0xFFFFu), etL = (int)(u >> 16);
        int ro = etL * NN + srcL;
        float a = __shfl_sync(FULLMASK, qv, etL) + __ldg(&g_kd[ro]);
        a = (a >= 0.f) ? a : 0.2f * a;
        float ex = valid ? __expf(a) : 0.f;
        ssum += ex;
        s_ro[warp][lane] = valid ? ro : 0;
        s_ex[warp][lane] = ex;
        __syncwarp();
        int mp = (m + 3) >> 2;
        #pragma unroll 4
        for (int j = 0; j < mp; j++) {
            int j2 = 4 * j + sub;
            int   roj = s_ro[warp][j2];
            float exj = s_ex[warp][j2];
            uint4 pk = *(const uint4*)(T + (size_t)roj * HH + 8 * c);
            float2 t0 = __half22float2(*(const __half2*)&pk.x);
            float2 t1 = __half22float2(*(const __half2*)&pk.y);
            float2 t2 = __half22float2(*(const __half2*)&pk.z);
            float2 t3 = __half22float2(*(const __half2*)&pk.w);
            acc[0] = fmaf(exj, t0.x, acc[0]); acc[1] = fmaf(exj, t0.y, acc[1]);
            acc[2] = fmaf(exj, t1.x, acc[2]); acc[3] = fmaf(exj, t1.y, acc[3]);
            acc[4] = fmaf(exj, t2.x, acc[4]); acc[5] = fmaf(exj, t2.y, acc[5]);
            acc[6] = fmaf(exj, t3.x, acc[6]); acc[7] = fmaf(exj, t3.y, acc[7]);
        }
        __syncwarp();
    }
    #pragma unroll
    for (int i = 0; i < 8; i++) {
        acc[i] += __shfl_xor_sync(FULLMASK, acc[i], 8);
        acc[i] += __shfl_xor_sync(FULLMASK, acc[i], 16);
    }
    #pragma unroll
    for (int o = 16; o; o >>= 1) ssum += __shfl_xor_sync(FULLMASK, ssum, o);
    float inv = 1.0f / (ssum + 1e-16f);
    if (sub == 0) {
        float4 bv0 = *(const float4*)(bias + 8 * c);
        float4 bv1 = *(const float4*)(bias + 8 * c + 4);
        float4 o0, o1;
        o0.x = fmaxf(acc[0] * inv + bv0.x, 0.f);
        o0.y = fmaxf(acc[1] * inv + bv0.y, 0.f);
        o0.z = fmaxf(acc[2] * inv + bv0.z, 0.f);
        o0.w = fmaxf(acc[3] * inv + bv0.w, 0.f);
        o1.x = fmaxf(acc[4] * inv + bv1.x, 0.f);
        o1.y = fmaxf(acc[5] * inv + bv1.y, 0.f);
        o1.z = fmaxf(acc[6] * inv + bv1.z, 0.f);
        o1.w = fmaxf(acc[7] * inv + bv1.w, 0.f);
        *(float4*)(outfeat + (size_t)n * HH + 8 * c)     = o0;
        *(float4*)(outfeat + (size_t)n * HH + 8 * c + 4) = o1;
    }
}

// ---------------- fused softmax + aggregation (mu & lv) + output linears ----------------
__global__ __launch_bounds__(256) void k_agg2(const __half* __restrict__ Tc,
                                              const float* __restrict__ bias_a,
                                              const float* __restrict__ bias_b,
                                              const float* __restrict__ Wm,
                                              const float* __restrict__ bm,
                                              const float* __restrict__ Wl,
                                              const float* __restrict__ bl,
                                              float* __restrict__ out) {
    __shared__ int   s_ro[8][32];
    __shared__ float s_ea[8][32];
    __shared__ float s_eb[8][32];
    __shared__ float s_rm[8][HH];
    __shared__ float s_rl[8][HH];
    __shared__ float sWm[HH * OUTD];
    __shared__ float sWl[HH * OUTD];
    int tid = threadIdx.x;
    for (int i = tid; i < HH * OUTD; i += 256) { sWm[i] = Wm[i]; sWl[i] = Wl[i]; }
    __syncthreads();

    int warp = tid >> 5, lane = tid & 31;
    int n = blockIdx.x * 8 + warp;
    if (n >= NN) return;
    int s0 = g_off[n], s1e = g_off[n + 1];
    float qva = (lane < RR) ? g_qd[lane * NN + n] : 0.f;
    float qvb = (lane < RR) ? g_qd[RR * NN + lane * NN + n] : 0.f;
    const int h = lane >> 4, c = lane & 15;
    float a0 = 0.f, a1 = 0.f, a2 = 0.f, a3 = 0.f, sa = 0.f;
    float b0 = 0.f, b1 = 0.f, b2 = 0.f, b3 = 0.f, sb = 0.f;
    for (int base = s0; base < s1e; base += 32) {
        int m = s1e - base; if (m > 32) m = 32;
        bool valid = (base + lane) < s1e;
        unsigned u = valid ? g_edges[base + lane] : 0u;
        int srcL = (int)(u & 0xFFFFu), etL = (int)(u >> 16);
        int ro = etL * NN + srcL;
        float2 kk = __ldg(&g_kd2[ro]);
        float la = __shfl_sync(FULLMASK, qva, etL) + kk.x;
        float lb = __shfl_sync(FULLMASK, qvb, etL) + kk.y;
        la = (la >= 0.f) ? la : 0.2f * la;
        lb = (lb >= 0.f) ? lb : 0.2f * lb;
        float exa = valid ? __expf(la) : 0.f;
        float exb = valid ? __expf(lb) : 0.f;
        sa += exa; sb += exb;
        s_ro[warp][lane] = valid ? ro : 0;
        s_ea[warp][lane] = exa;
        s_eb[warp][lane] = exb;
        __syncwarp();
        int mp = (m + 1) >> 1;
        #pragma unroll 8
        for (int j = 0; j < mp; j++) {
            int j2 = 2 * j + h;
            int   roj = s_ro[warp][j2];
            float ea  = s_ea[warp][j2];
            float eb  = s_eb[warp][j2];
            uint4 pk = *(const uint4*)(Tc + (size_t)roj * 128 + 8 * c);
            float2 ta0 = __half22float2(*(const __half2*)&pk.x);
            float2 tb0 = __half22float2(*(const __half2*)&pk.y);
            float2 ta1 = __half22float2(*(const __half2*)&pk.z);
            float2 tb1 = __half22float2(*(const __half2*)&pk.w);
            a0 = fmaf(ea, ta0.x, a0); a1 = fmaf(ea, ta0.y, a1);
            a2 = fmaf(ea, ta1.x, a2); a3 = fmaf(ea, ta1.y, a3);
            b0 = fmaf(eb, tb0.x, b0); b1 = fmaf(eb, tb0.y, b1);
            b2 = fmaf(eb, tb1.x, b2); b3 = fmaf(eb, tb1.y, b3);
        }
        __syncwarp();
    }
    a0 += __shfl_xor_sync(FULLMASK, a0, 16);
    a1 += __shfl_xor_sync(FULLMASK, a1, 16);
    a2 += __shfl_xor_sync(FULLMASK, a2, 16);
    a3 += __shfl_xor_sync(FULLMASK, a3, 16);
    b0 += __shfl_xor_sync(FULLMASK, b0, 16);
    b1 += __shfl_xor_sync(FULLMASK, b1, 16);
    b2 += __shfl_xor_sync(FULLMASK, b2, 16);
    b3 += __shfl_xor_sync(FULLMASK, b3, 16);
    #pragma unroll
    for (int o = 16; o; o >>= 1) {
        sa += __shfl_xor_sync(FULLMASK, sa, o);
        sb += __shfl_xor_sync(FULLMASK, sb, o);
    }
    float ia = 1.0f / (sa + 1e-16f);
    float ib = 1.0f / (sb + 1e-16f);
    if (h == 0) {
        float4 bva = *(const float4*)(bias_a + 4 * c);
        float4 bvb = *(const float4*)(bias_b + 4 * c);
        float4 oa, ob;
        oa.x = fmaxf(a0 * ia + bva.x, 0.f);
        oa.y = fmaxf(a1 * ia + bva.y, 0.f);
        oa.z = fmaxf(a2 * ia + bva.z, 0.f);
        oa.w = fmaxf(a3 * ia + bva.w, 0.f);
        ob.x = fmaxf(b0 * ib + bvb.x, 0.f);
        ob.y = fmaxf(b1 * ib + bvb.y, 0.f);
        ob.z = fmaxf(b2 * ib + bvb.z, 0.f);
        ob.w = fmaxf(b3 * ib + bvb.w, 0.f);
        *(float4*)&s_rm[warp][4 * c] = oa;
        *(float4*)&s_rl[warp][4 * c] = ob;
    }
    __syncwarp();
    float am = 0.f, al = 0.f;
    #pragma unroll 8
    for (int k = 0; k < HH; k++) {
        float rm = s_rm[warp][k];
        float rl = s_rl[warp][k];
        am = fmaf(rm, sWm[k * OUTD + lane], am);
        al = fmaf(rl, sWl[k * OUTD + lane], al);
    }
    out[(size_t)n * OUTD + lane] = am + __ldg(&bm[lane]);
    out[(size_t)NN * OUTD + (size_t)n * OUTD + lane] = 0.5f * (al + __ldg(&bl[lane]));
}

// ---------------- launch ----------------
extern "C" void kernel_launch(void* const* d_in, const int* in_sizes, int n_in,
                              void* d_out, int out_size) {
    const float* x   = (const float*)d_in[0];
    const int*   ei  = (const int*)d_in[1];
    const int*   et  = (const int*)d_in[2];
    const float* W1  = (const float*)d_in[3];
    const float* q1  = (const float*)d_in[4];
    const float* k1  = (const float*)d_in[5];
    const float* b1  = (const float*)d_in[6];
    const float* Wmu = (const float*)d_in[7];
    const float* qmu = (const float*)d_in[8];
    const float* kmu = (const float*)d_in[9];
    const float* bmu = (const float*)d_in[10];
    const float* Wlv = (const float*)d_in[11];
    const float* qlv = (const float*)d_in[12];
    const float* klv = (const float*)d_in[13];
    const float* blv = (const float*)d_in[14];
    const float* Wm  = (const float*)d_in[15];
    const float* bm  = (const float*)d_in[16];
    const float* Wl  = (const float*)d_in[17];
    const float* bl  = (const float*)d_in[18];
    const int* src = ei;
    const int* dst = ei + EE;
    float* out = (float*)d_out;

    float*  hidden; cudaGetSymbolAddress((void**)&hidden, g_hidden);
    __half* ta;     cudaGetSymbolAddress((void**)&ta, g_ta);
    __half* tc;     cudaGetSymbolAddress((void**)&tc, g_tc);

    static cudaStream_t s1 = nullptr, s2 = nullptr;
    static cudaEvent_t evFork, evCSR, evHid, evQd2, evQd1;
    if (!s1) {
        cudaStreamCreateWithFlags(&s1, cudaStreamNonBlocking);
        cudaStreamCreateWithFlags(&s2, cudaStreamNonBlocking);
        cudaEventCreateWithFlags(&evFork, cudaEventDisableTiming);
        cudaEventCreateWithFlags(&evCSR,  cudaEventDisableTiming);
        cudaEventCreateWithFlags(&evHid,  cudaEventDisableTiming);
        cudaEventCreateWithFlags(&evQd2,  cudaEventDisableTiming);
        cudaEventCreateWithFlags(&evQd1,  cudaEventDisableTiming);
    }

    const int TB = 256;
    dim3 gemm_grid((NN + BM - 1) / BM, RR);
    int node_warp_blocks = (NN + 7) / 8;

    // ---- fork: CSR on s1; wqwk3->qdkd on s2; gemm1 immediately on main ----
    cudaEventRecord(evFork, 0);
    cudaStreamWaitEvent(s1, evFork, 0);
    cudaStreamWaitEvent(s2, evFork, 0);
    k_zero_off<<<(NN + 1 + TB - 1) / TB, TB, 0, s1>>>();
    k_wqwk3<<<3, TB, 0, s2>>>(W1, q1, k1, Wmu, qmu, kmu, Wlv, qlv, klv);
    k_qdkd<<<node_warp_blocks, TB, 0, s2>>>(x, DIN1);
    cudaEventRecord(evQd1, s2);

    k_gemm<<<gemm_grid, TB>>>(x, W1, ta, DIN1);

    k_hist<<<EE / TB, TB, 0, s1>>>(dst);
    k_scan<<<1, 1024, 0, s1>>>();
    k_scatter<<<EE / TB, TB, 0, s1>>>(src, dst, et);
    cudaEventRecord(evCSR, s1);

    // ---- join CSR + qdkd1, layer-1 aggregation ----
    cudaStreamWaitEvent(0, evCSR, 0);
    cudaStreamWaitEvent(0, evQd1, 0);
    k_agg<<<node_warp_blocks, TB>>>(ta, b1, hidden);
    cudaEventRecord(evHid, 0);

    // ---- qdkd2 on s1, concurrent with gemm2 ----
    cudaStreamWaitEvent(s1, evHid, 0);
    k_qdkd2<<<node_warp_blocks, TB, 0, s1>>>(hidden);
    cudaEventRecord(evQd2, s1);

    k_gemm2<<<gemm_grid, TB>>>(hidden, Wmu, Wlv, tc);
    cudaStreamWaitEvent(0, evQd2, 0);
    k_agg2<<<node_warp_blocks, TB>>>(tc, bmu, blv, Wm, bm, Wl, bl, out);
}

// round 16
// speedup vs baseline: 1.2425x; 1.0049x over previous
#include <cuda_runtime.h>
#include <cuda_fp16.h>
#include <cstdint>

#define NN 50000
#define EE 1600000
#define RR 8
#define DIN1 128
#define HH 64
#define OUTD 32
#define FULLMASK 0xffffffffu

// ---------------- scratch (static device globals; allocation-free) ----------------
__device__ __half   g_ta[(size_t)RR * NN * HH];        // layer-1 transformed feats (fp16)
__device__ __half   g_tc[(size_t)RR * NN * 2 * HH];    // mu/lv interleaved: row=128 halves
__device__ float    g_qd[2 * RR * NN];
__device__ float    g_kd[RR * NN];                     // layer-1 kd
__device__ float2   g_kd2[RR * NN];                    // (kd_mu, kd_lv)
__device__ float    g_wq[3 * RR * DIN1];               // set 0: layer1, 1: mu, 2: lv
__device__ float    g_wk[3 * RR * DIN1];
__device__ float    g_hidden[NN * HH];
__device__ int      g_off[NN + 1];
__device__ int      g_cursor[NN];
__device__ unsigned g_edges[EE];                       // src | (etype<<16)

// ---------------- CSR build ----------------
__global__ void k_hist(const int* __restrict__ dst) {
    int e = blockIdx.x * blockDim.x + threadIdx.x;
    if (e < EE) atomicAdd(&g_off[dst[e]], 1);
}

__global__ void k_scan() {
    __shared__ int wsum[32];
    const int tid = threadIdx.x, lane = tid & 31, wid = tid >> 5;
    int carry = 0;
    for (int base = 0; base < NN; base += 1024) {
        int i = base + tid;
        int v = (i < NN) ? g_off[i] : 0;
        int s = v;
        #pragma unroll
        for (int o = 1; o < 32; o <<= 1) {
            int t = __shfl_up_sync(FULLMASK, s, o);
            if (lane >= o) s += t;
        }
        if (lane == 31) wsum[wid] = s;
        __syncthreads();
        if (wid == 0) {
            int ws = wsum[lane];
            #pragma unroll
            for (int o = 1; o < 32; o <<= 1) {
                int t = __shfl_up_sync(FULLMASK, ws, o);
                if (lane >= o) ws += t;
            }
            wsum[lane] = ws;
        }
        __syncthreads();
        int excl = s - v + (wid ? wsum[wid - 1] : 0) + carry;
        if (i < NN) { g_off[i] = excl; g_cursor[i] = excl; }
        int total = wsum[31];
        __syncthreads();
        carry += total;
    }
    if (tid == 0) g_off[NN] = carry;
}

__global__ void k_scatter(const int* __restrict__ src, const int* __restrict__ dst,
                          const int* __restrict__ et) {
    int e = blockIdx.x * blockDim.x + threadIdx.x;
    if (e < EE) {
        int pos = atomicAdd(&g_cursor[dst[e]], 1);
        g_edges[pos] = (unsigned)src[e] | ((unsigned)et[e] << 16);
    }
}

// ---------------- all three wq/wk sets in one kernel (blockIdx.x = set) ----------------
__global__ void k_wqwk3(const float* __restrict__ W1, const float* __restrict__ q1,
                        const float* __restrict__ k1,
                        const float* __restrict__ Wmu, const float* __restrict__ qmu,
                        const float* __restrict__ kmu,
                        const float* __restrict__ Wlv, const float* __restrict__ qlv,
                        const float* __restrict__ klv) {
    const int set = blockIdx.x;
    const float* W = (set == 0) ? W1 : (set == 1) ? Wmu : Wlv;
    const float* q = (set == 0) ? q1 : (set == 1) ? qmu : qlv;
    const float* k = (set == 0) ? k1 : (set == 1) ? kmu : klv;
    const int Din = (set == 0) ? DIN1 : HH;
    __shared__ float qs[HH], ks[HH];
    if (threadIdx.x < HH) { qs[threadIdx.x] = q[threadIdx.x]; ks[threadIdx.x] = k[threadIdx.x]; }
    __syncthreads();
    for (int e = threadIdx.x; e < RR * Din; e += blockDim.x) {
        const float* w = W + (size_t)e * HH;
        float aq = 0.f, ak = 0.f;
        #pragma unroll 8
        for (int o = 0; o < HH; o++) { float wv = w[o]; aq += wv * qs[o]; ak += wv * ks[o]; }
        g_wq[set * RR * DIN1 + e] = aq;
        g_wk[set * RR * DIN1 + e] = ak;
    }
}

// ---------------- fp16 mma helpers ----------------
__device__ __forceinline__ unsigned packh2(float a, float b) {
    __half2 h = __floats2half2_rn(a, b);
    return *(unsigned*)&h;
}

__device__ __forceinline__ void mma_fp16(float* d, const unsigned* a, const unsigned* b) {
    asm volatile(
        "mma.sync.aligned.m16n8k16.row.col.f32.f16.f16.f32 "
        "{%0,%1,%2,%3}, {%4,%5,%6,%7}, {%8,%9}, {%0,%1,%2,%3};\n"
        : "+f"(d[0]), "+f"(d[1]), "+f"(d[2]), "+f"(d[3])
        : "r"(a[0]), "r"(a[1]), "r"(a[2]), "r"(a[3]), "r"(b[0]), "r"(b[1]));
}

__device__ __forceinline__ void ldsm_x4(unsigned* r, uint32_t addr) {
    asm volatile("ldmatrix.sync.aligned.m8n8.x4.shared.b16 {%0,%1,%2,%3}, [%4];"
                 : "=r"(r[0]), "=r"(r[1]), "=r"(r[2]), "=r"(r[3]) : "r"(addr));
}

// ---------------- GEMM layer 1 (fp16 mma + ldmatrix A, double-buffered) ----------------
#define BM 128
#define BK 16
__global__ __launch_bounds__(256) void k_gemm(const float* __restrict__ X,
                                              const float* __restrict__ W,
                                              __half* __restrict__ T, int Din) {
    const int r  = blockIdx.y;
    const int m0 = blockIdx.x * BM;
    __shared__ unsigned As[2][BM][12];
    __shared__ unsigned Bs[2][8][HH + 8];
    const int tid  = threadIdx.x;
    const int warp = tid >> 5, lane = tid & 31;
    const int wm = (warp & 3) * 32;
    const int wn = (warp >> 2) * 32;
    const int gid = lane >> 2, tig = lane & 3;
    float acc[2][4][4] = {};
    const float* Wr = W + (size_t)r * Din * HH;

    const int a_row  = tid >> 1;
    const int a_half = tid & 1;
    const int b_kp   = tid >> 5;
    const int b_n    = (tid & 31) * 2;
    const int gm_a   = m0 + a_row;
    const int nk = Din / BK;

    const int lrow = (lane & 7) + ((lane >> 3) & 1) * 8;
    const int lcol = (lane >> 4) * 4;
    const uint32_t a_base = (uint32_t)__cvta_generic_to_shared(&As[0][0][0]);

    float4 va0, va1;
    float2 r0, r1;
    {
        if (gm_a < NN) {
            const float* p = X + (size_t)gm_a * Din + a_half * 8;
            va0 = *(const float4*)p; va1 = *(const float4*)(p + 4);
        } else { va0 = make_float4(0.f,0.f,0.f,0.f); va1 = va0; }
        r0 = *(const float2*)(Wr + (size_t)(2 * b_kp)     * HH + b_n);
        r1 = *(const float2*)(Wr + (size_t)(2 * b_kp + 1) * HH + b_n);
    }
    {
        *(uint4*)&As[0][a_row][a_half * 4] = make_uint4(
            packh2(va0.x, va0.y), packh2(va0.z, va0.w),
            packh2(va1.x, va1.y), packh2(va1.z, va1.w));
        *(uint2*)&Bs[0][b_kp][b_n] = make_uint2(packh2(r0.x, r1.x), packh2(r0.y, r1.y));
    }
    __syncthreads();

    for (int kt = 0; kt < nk; kt++) {
        const int cur = kt & 1;
        if (kt + 1 < nk) {
            int k0 = (kt + 1) * BK;
            if (gm_a < NN) {
                const float* p = X + (size_t)gm_a * Din + k0 + a_half * 8;
                va0 = *(const float4*)p; va1 = *(const float4*)(p + 4);
            } else { va0 = make_float4(0.f,0.f,0.f,0.f); va1 = va0; }
            r0 = *(const float2*)(Wr + (size_t)(k0 + 2 * b_kp)     * HH + b_n);
            r1 = *(const float2*)(Wr + (size_t)(k0 + 2 * b_kp + 1) * HH + b_n);
        }
        {
            unsigned a[2][4], b[4][2];
            #pragma unroll
            for (int mf = 0; mf < 2; mf++) {
                int mr = wm + mf * 16;
                uint32_t addr = a_base + ((uint32_t)((cur * BM + mr + lrow) * 12 + lcol) << 2);
                ldsm_x4(a[mf], addr);
            }
            #pragma unroll
            for (int nf = 0; nf < 4; nf++) {
                int nc = wn + nf * 8;
                b[nf][0] = Bs[cur][tig    ][nc + gid];
                b[nf][1] = Bs[cur][tig + 4][nc + gid];
            }
            #pragma unroll
            for (int mf = 0; mf < 2; mf++)
                #pragma unroll
                for (int nf = 0; nf < 4; nf++)
                    mma_fp16(acc[mf][nf], a[mf], b[nf]);
        }
        if (kt + 1 < nk) {
            const int nxt = (kt + 1) & 1;
            *(uint4*)&As[nxt][a_row][a_half * 4] = make_uint4(
                packh2(va0.x, va0.y), packh2(va0.z, va0.w),
                packh2(va1.x, va1.y), packh2(va1.z, va1.w));
            *(uint2*)&Bs[nxt][b_kp][b_n] = make_uint2(packh2(r0.x, r1.x), packh2(r0.y, r1.y));
            __syncthreads();
        }
    }

    #pragma unroll
    for (int mf = 0; mf < 2; mf++) {
        #pragma unroll
        for (int nf = 0; nf < 4; nf++) {
            int col = wn + nf * 8 + tig * 2;
            int gm0 = m0 + wm + mf * 16 + gid;
            int gm1 = gm0 + 8;
            if (gm0 < NN)
                *(__half2*)&T[((size_t)r * NN + gm0) * HH + col] =
                    __floats2half2_rn(acc[mf][nf][0], acc[mf][nf][1]);
            if (gm1 < NN)
                *(__half2*)&T[((size_t)r * NN + gm1) * HH + col] =
                    __floats2half2_rn(acc[mf][nf][2], acc[mf][nf][3]);
        }
    }
}

// ---------------- GEMM dual (fp16 mma + ldmatrix A, mu & lv): Tc interleaved ----------------
__global__ __launch_bounds__(256) void k_gemm2(const float* __restrict__ X,
                                               const float* __restrict__ Wa,
                                               const float* __restrict__ Wb,
                                               __half* __restrict__ Tc) {
    const int r  = blockIdx.y;
    const int m0 = blockIdx.x * BM;
    __shared__ unsigned As[2][BM][12];
    __shared__ unsigned Bs[2][2][8][HH + 8];
    const int tid  = threadIdx.x;
    const int warp = tid >> 5, lane = tid & 31;
    const int wm = (warp & 3) * 32;
    const int wn = (warp >> 2) * 32;
    const int gid = lane >> 2, tig = lane & 3;
    float acc[2][2][4][4] = {};
    const float* WrA = Wa + (size_t)r * HH * HH;
    const float* WrB = Wb + (size_t)r * HH * HH;

    const int a_row  = tid >> 1;
    const int a_half = tid & 1;
    const int b_kp   = tid >> 5;
    const int b_n    = (tid & 31) * 2;
    const int gm_a   = m0 + a_row;
    const int nk = HH / BK;

    const int lrow = (lane & 7) + ((lane >> 3) & 1) * 8;
    const int lcol = (lane >> 4) * 4;
    const uint32_t a_base = (uint32_t)__cvta_generic_to_shared(&As[0][0][0]);

    float4 va0, va1;
    float2 ra0, ra1, rb0, rb1;
    {
        if (gm_a < NN) {
            const float* p = X + (size_t)gm_a * HH + a_half * 8;
            va0 = *(const float4*)p; va1 = *(const float4*)(p + 4);
        } else { va0 = make_float4(0.f,0.f,0.f,0.f); va1 = va0; }
        size_t o0 = (size_t)(2 * b_kp) * HH + b_n;
        size_t o1 = (size_t)(2 * b_kp + 1) * HH + b_n;
        ra0 = *(const float2*)(WrA + o0); ra1 = *(const float2*)(WrA + o1);
        rb0 = *(const float2*)(WrB + o0); rb1 = *(const float2*)(WrB + o1);
    }
    {
        *(uint4*)&As[0][a_row][a_half * 4] = make_uint4(
            packh2(va0.x, va0.y), packh2(va0.z, va0.w),
            packh2(va1.x, va1.y), packh2(va1.z, va1.w));
        *(uint2*)&Bs[0][0][b_kp][b_n] = make_uint2(packh2(ra0.x, ra1.x), packh2(ra0.y, ra1.y));
        *(uint2*)&Bs[0][1][b_kp][b_n] = make_uint2(packh2(rb0.x, rb1.x), packh2(rb0.y, rb1.y));
    }
    __syncthreads();

    for (int kt = 0; kt < nk; kt++) {
        const int cur = kt & 1;
        if (kt + 1 < nk) {
            int k0 = (kt + 1) * BK;
            if (gm_a < NN) {
                const float* p = X + (size_t)gm_a * HH + k0 + a_half * 8;
                va0 = *(const float4*)p; va1 = *(const float4*)(p + 4);
            } else { va0 = make_float4(0.f,0.f,0.f,0.f); va1 = va0; }
            size_t o0 = (size_t)(k0 + 2 * b_kp) * HH + b_n;
            size_t o1 = (size_t)(k0 + 2 * b_kp + 1) * HH + b_n;
            ra0 = *(const float2*)(WrA + o0); ra1 = *(const float2*)(WrA + o1);
            rb0 = *(const float2*)(WrB + o0); rb1 = *(const float2*)(WrB + o1);
        }
        {
            unsigned a[2][4];
            #pragma unroll
            for (int mf = 0; mf < 2; mf++) {
                int mr = wm + mf * 16;
                uint32_t addr = a_base + ((uint32_t)((cur * BM + mr + lrow) * 12 + lcol) << 2);
                ldsm_x4(a[mf], addr);
            }
            #pragma unroll
            for (int s = 0; s < 2; s++) {
                unsigned b[4][2];
                #pragma unroll
                for (int nf = 0; nf < 4; nf++) {
                    int nc = wn + nf * 8;
                    b[nf][0] = Bs[cur][s][tig    ][nc + gid];
                    b[nf][1] = Bs[cur][s][tig + 4][nc + gid];
                }
                #pragma unroll
                for (int mf = 0; mf < 2; mf++)
                    #pragma unroll
                    for (int nf = 0; nf < 4; nf++)
                        mma_fp16(acc[s][mf][nf], a[mf], b[nf]);
            }
        }
        if (kt + 1 < nk) {
            const int nxt = (kt + 1) & 1;
            *(uint4*)&As[nxt][a_row][a_half * 4] = make_uint4(
                packh2(va0.x, va0.y), packh2(va0.z, va0.w),
                packh2(va1.x, va1.y), packh2(va1.z, va1.w));
            *(uint2*)&Bs[nxt][0][b_kp][b_n] = make_uint2(packh2(ra0.x, ra1.x), packh2(ra0.y, ra1.y));
            *(uint2*)&Bs[nxt][1][b_kp][b_n] = make_uint2(packh2(rb0.x, rb1.x), packh2(rb0.y, rb1.y));
            __syncthreads();
        }
    }

    #pragma unroll
    for (int s = 0; s < 2; s++) {
        #pragma unroll
        for (int mf = 0; mf < 2; mf++) {
            #pragma unroll
            for (int nf = 0; nf < 4; nf++) {
                int col = wn + nf * 8 + tig * 2;
                int p   = col >> 1;
                int gm0 = m0 + wm + mf * 16 + gid;
                int gm1 = gm0 + 8;
                if (gm0 < NN)
                    *(__half2*)&Tc[((size_t)(r * NN + gm0)) * 128 + 4 * p + 2 * s] =
                        __floats2half2_rn(acc[s][mf][nf][0], acc[s][mf][nf][1]);
                if (gm1 < NN)
                    *(__half2*)&Tc[((size_t)(r * NN + gm1)) * 128 + 4 * p + 2 * s] =
                        __floats2half2_rn(acc[s][mf][nf][2], acc[s][mf][nf][3]);
            }
        }
    }
}

// ---------------- per-node attention scalars (layer 1, set 0) ----------------
__global__ __launch_bounds__(256) void k_qdkd(const float* __restrict__ X, int Din) {
    __shared__ float swq[RR * DIN1], swk[RR * DIN1];
    int nb = RR * Din;
    for (int i = threadIdx.x; i < nb; i += 256) { swq[i] = g_wq[i]; swk[i] = g_wk[i]; }
    __syncthreads();
    int warp = threadIdx.x >> 5, lane = threadIdx.x & 31;
    int n = blockIdx.x * 8 + warp;
    if (n >= NN) return;
    float xv[4];
    int L = Din >> 5;
    #pragma unroll
    for (int l = 0; l < 4; l++)
        xv[l] = (l < L) ? X[(size_t)n * Din + lane + 32 * l] : 0.f;
    #pragma unroll
    for (int r = 0; r < RR; r++) {
        float aq = 0.f, ak = 0.f;
        #pragma unroll
        for (int l = 0; l < 4; l++) {
            if (l < L) {
                aq = fmaf(xv[l], swq[r * Din + lane + 32 * l], aq);
                ak = fmaf(xv[l], swk[r * Din + lane + 32 * l], ak);
            }
        }
        #pragma unroll
        for (int o = 16; o; o >>= 1) {
            aq += __shfl_down_sync(FULLMASK, aq, o);
            ak += __shfl_down_sync(FULLMASK, ak, o);
        }
        if (lane == 0) { g_qd[r * NN + n] = aq; g_kd[r * NN + n] = ak; }
    }
}

// ---------------- per-node attention scalars (mu set 1 & lv set 2, Din=HH) ----------------
__global__ __launch_bounds__(256) void k_qdkd2(const float* __restrict__ X) {
    __shared__ float swq[2][RR * HH], swk[2][RR * HH];
    for (int i = threadIdx.x; i < RR * HH; i += 256) {
        swq[0][i] = g_wq[RR * DIN1 + i];        swk[0][i] = g_wk[RR * DIN1 + i];
        swq[1][i] = g_wq[2 * RR * DIN1 + i];    swk[1][i] = g_wk[2 * RR * DIN1 + i];
    }
    __syncthreads();
    int warp = threadIdx.x >> 5, lane = threadIdx.x & 31;
    int n = blockIdx.x * 8 + warp;
    if (n >= NN) return;
    float x0 = X[(size_t)n * HH + lane];
    float x1 = X[(size_t)n * HH + lane + 32];
    #pragma unroll
    for (int r = 0; r < RR; r++) {
        float aq0 = x0 * swq[0][r * HH + lane] + x1 * swq[0][r * HH + lane + 32];
        float ak0 = x0 * swk[0][r * HH + lane] + x1 * swk[0][r * HH + lane + 32];
        float aq1 = x0 * swq[1][r * HH + lane] + x1 * swq[1][r * HH + lane + 32];
        float ak1 = x0 * swk[1][r * HH + lane] + x1 * swk[1][r * HH + lane + 32];
        #pragma unroll
        for (int o = 16; o; o >>= 1) {
            aq0 += __shfl_down_sync(FULLMASK, aq0, o);
            ak0 += __shfl_down_sync(FULLMASK, ak0, o);
            aq1 += __shfl_down_sync(FULLMASK, aq1, o);
            ak1 += __shfl_down_sync(FULLMASK, ak1, o);
        }
        if (lane == 0) {
            g_qd[r * NN + n] = aq0;
            g_qd[RR * NN + r * NN + n] = aq1;
            g_kd2[r * NN + n] = make_float2(ak0, ak1);
        }
    }
}

// ---------------- fused softmax + aggregation (layer 1); 4 edges per j-iter ----------------
__global__ __launch_bounds__(256) void k_agg(const __half* __restrict__ T,
                                             const float* __restrict__ bias,
                                             float* __restrict__ outfeat) {
    __shared__ int   s_ro[8][32];
    __shared__ float s_ex[8][32];
    int warp = threadIdx.x >> 5, lane = threadIdx.x & 31;
    int n = blockIdx.x * 8 + warp;
    if (n >= NN) return;
    int s0 = g_off[n], s1e = g_off[n + 1];
    float qv = (lane < RR) ? g_qd[lane * NN + n] : 0.f;
    const int sub = lane >> 3;
    const int c   = lane & 7;
    float acc[8] = {};
    float ssum = 0.f;
    for (int base = s0; base < s1e; base += 32) {
        int m = s1e - base; if (m > 32) m = 32;
        bool valid = (base + lane) < s1e;
        unsigned u = valid ? g_edges[base + lane] : 0u;
        int srcL = (int)(u & 0xFFFFu), etL = (int)(u >> 16);
        int ro = etL * NN + srcL;
        float a = __shfl_sync(FULLMASK, qv, etL) + __ldg(&g_kd[ro]);
        a = (a >= 0.f) ? a : 0.2f * a;
        float ex = valid ? __expf(a) : 0.f;
        ssum += ex;
        s_ro[warp][lane] = valid ? ro : 0;
        s_ex[warp][lane] = ex;
        __syncwarp();
        int mp = (m + 3) >> 2;
        #pragma unroll 4
        for (int j = 0; j < mp; j++) {
            int j2 = 4 * j + sub;
            int   roj = s_ro[warp][j2];
            float exj = s_ex[warp][j2];
            uint4 pk = *(const uint4*)(T + (size_t)roj * HH + 8 * c);
            float2 t0 = __half22float2(*(const __half2*)&pk.x);
            float2 t1 = __half22float2(*(const __half2*)&pk.y);
            float2 t2 = __half22float2(*(const __half2*)&pk.z);
            float2 t3 = __half22float2(*(const __half2*)&pk.w);
            acc[0] = fmaf(exj, t0.x, acc[0]); acc[1] = fmaf(exj, t0.y, acc[1]);
            acc[2] = fmaf(exj, t1.x, acc[2]); acc[3] = fmaf(exj, t1.y, acc[3]);
            acc[4] = fmaf(exj, t2.x, acc[4]); acc[5] = fmaf(exj, t2.y, acc[5]);
            acc[6] = fmaf(exj, t3.x, acc[6]); acc[7] = fmaf(exj, t3.y, acc[7]);
        }
        __syncwarp();
    }
    #pragma unroll
    for (int i = 0; i < 8; i++) {
        acc[i] += __shfl_xor_sync(FULLMASK, acc[i], 8);
        acc[i] += __shfl_xor_sync(FULLMASK, acc[i], 16);
    }
    #pragma unroll
    for (int o = 16; o; o >>= 1) ssum += __shfl_xor_sync(FULLMASK, ssum, o);
    float inv = 1.0f / (ssum + 1e-16f);
    if (sub == 0) {
        float4 bv0 = *(const float4*)(bias + 8 * c);
        float4 bv1 = *(const float4*)(bias + 8 * c + 4);
        float4 o0, o1;
        o0.x = fmaxf(acc[0] * inv + bv0.x, 0.f);
        o0.y = fmaxf(acc[1] * inv + bv0.y, 0.f);
        o0.z = fmaxf(acc[2] * inv + bv0.z, 0.f);
        o0.w = fmaxf(acc[3] * inv + bv0.w, 0.f);
        o1.x = fmaxf(acc[4] * inv + bv1.x, 0.f);
        o1.y = fmaxf(acc[5] * inv + bv1.y, 0.f);
        o1.z = fmaxf(acc[6] * inv + bv1.z, 0.f);
        o1.w = fmaxf(acc[7] * inv + bv1.w, 0.f);
        *(float4*)(outfeat + (size_t)n * HH + 8 * c)     = o0;
        *(float4*)(outfeat + (size_t)n * HH + 8 * c + 4) = o1;
    }
}

// ---------------- fused softmax + aggregation (mu & lv) + output linears ----------------
// 4 nodes per warp (amortizes the 16KB weight staging across 4x work)
__global__ __launch_bounds__(256) void k_agg2(const __half* __restrict__ Tc,
                                              const float* __restrict__ bias_a,
                                              const float* __restrict__ bias_b,
                                              const float* __restrict__ Wm,
                                              const float* __restrict__ bm,
                                              const float* __restrict__ Wl,
                                              const float* __restrict__ bl,
                                              float* __restrict__ out) {
    __shared__ int   s_ro[8][32];
    __shared__ float s_ea[8][32];
    __shared__ float s_eb[8][32];
    __shared__ float s_rm[8][HH];
    __shared__ float s_rl[8][HH];
    __shared__ float sWm[HH * OUTD];
    __shared__ float sWl[HH * OUTD];
    int tid = threadIdx.x;
    for (int i = tid; i < HH * OUTD; i += 256) { sWm[i] = Wm[i]; sWl[i] = Wl[i]; }
    __syncthreads();

    int warp = tid >> 5, lane = tid & 31;
    const int h = lane >> 4, c = lane & 15;

    for (int it = 0; it < 4; it++) {
        int n = blockIdx.x * 32 + it * 8 + warp;
        if (n >= NN) continue;
        int s0 = g_off[n], s1e = g_off[n + 1];
        float qva = (lane < RR) ? g_qd[lane * NN + n] : 0.f;
        float qvb = (lane < RR) ? g_qd[RR * NN + lane * NN + n] : 0.f;
        float a0 = 0.f, a1 = 0.f, a2 = 0.f, a3 = 0.f, sa = 0.f;
        float b0 = 0.f, b1 = 0.f, b2 = 0.f, b3 = 0.f, sb = 0.f;
        for (int base = s0; base < s1e; base += 32) {
            int m = s1e - base; if (m > 32) m = 32;
            bool valid = (base + lane) < s1e;
            unsigned u = valid ? g_edges[base + lane] : 0u;
            int srcL = (int)(u & 0xFFFFu), etL = (int)(u >> 16);
            int ro = etL * NN + srcL;
            float2 kk = __ldg(&g_kd2[ro]);
            float la = __shfl_sync(FULLMASK, qva, etL) + kk.x;
            float lb = __shfl_sync(FULLMASK, qvb, etL) + kk.y;
            la = (la >= 0.f) ? la : 0.2f * la;
            lb = (lb >= 0.f) ? lb : 0.2f * lb;
            float exa = valid ? __expf(la) : 0.f;
            float exb = valid ? __expf(lb) : 0.f;
            sa += exa; sb += exb;
            s_ro[warp][lane] = valid ? ro : 0;
            s_ea[warp][lane] = exa;
            s_eb[warp][lane] = exb;
            __syncwarp();
            int mp = (m + 1) >> 1;
            #pragma unroll 8
            for (int j = 0; j < mp; j++) {
                int j2 = 2 * j + h;
                int   roj = s_ro[warp][j2];
                float ea  = s_ea[warp][j2];
                float eb  = s_eb[warp][j2];
                uint4 pk = *(const uint4*)(Tc + (size_t)roj * 128 + 8 * c);
                float2 ta0 = __half22float2(*(const __half2*)&pk.x);
                float2 tb0 = __half22float2(*(const __half2*)&pk.y);
                float2 ta1 = __half22float2(*(const __half2*)&pk.z);
                float2 tb1 = __half22float2(*(const __half2*)&pk.w);
                a0 = fmaf(ea, ta0.x, a0); a1 = fmaf(ea, ta0.y, a1);
                a2 = fmaf(ea, ta1.x, a2); a3 = fmaf(ea, ta1.y, a3);
                b0 = fmaf(eb, tb0.x, b0); b1 = fmaf(eb, tb0.y, b1);
                b2 = fmaf(eb, tb1.x, b2); b3 = fmaf(eb, tb1.y, b3);
            }
            __syncwarp();
        }
        a0 += __shfl_xor_sync(FULLMASK, a0, 16);
        a1 += __shfl_xor_sync(FULLMASK, a1, 16);
        a2 += __shfl_xor_sync(FULLMASK, a2, 16);
        a3 += __shfl_xor_sync(FULLMASK, a3, 16);
        b0 += __shfl_xor_sync(FULLMASK, b0, 16);
        b1 += __shfl_xor_sync(FULLMASK, b1, 16);
        b2 += __shfl_xor_sync(FULLMASK, b2, 16);
        b3 += __shfl_xor_sync(FULLMASK, b3, 16);
        #pragma unroll
        for (int o = 16; o; o >>= 1) {
            sa += __shfl_xor_sync(FULLMASK, sa, o);
            sb += __shfl_xor_sync(FULLMASK, sb, o);
        }
        float ia = 1.0f / (sa + 1e-16f);
        float ib = 1.0f / (sb + 1e-16f);
        if (h == 0) {
            float4 bva = *(const float4*)(bias_a + 4 * c);
            float4 bvb = *(const float4*)(bias_b + 4 * c);
            float4 oa, ob;
            oa.x = fmaxf(a0 * ia + bva.x, 0.f);
            oa.y = fmaxf(a1 * ia + bva.y, 0.f);
            oa.z = fmaxf(a2 * ia + bva.z, 0.f);
            oa.w = fmaxf(a3 * ia + bva.w, 0.f);
            ob.x = fmaxf(b0 * ib + bvb.x, 0.f);
            ob.y = fmaxf(b1 * ib + bvb.y, 0.f);
            ob.z = fmaxf(b2 * ib + bvb.z, 0.f);
            ob.w = fmaxf(b3 * ib + bvb.w, 0.f);
            *(float4*)&s_rm[warp][4 * c] = oa;
            *(float4*)&s_rl[warp][4 * c] = ob;
        }
        __syncwarp();
        float am = 0.f, al = 0.f;
        #pragma unroll 8
        for (int k = 0; k < HH; k++) {
            float rm = s_rm[warp][k];
            float rl = s_rl[warp][k];
            am = fmaf(rm, sWm[k * OUTD + lane], am);
            al = fmaf(rl, sWl[k * OUTD + lane], al);
        }
        out[(size_t)n * OUTD + lane] = am + __ldg(&bm[lane]);
        out[(size_t)NN * OUTD + (size_t)n * OUTD + lane] = 0.5f * (al + __ldg(&bl[lane]));
        __syncwarp();
    }
}

// ---------------- launch ----------------
extern "C" void kernel_launch(void* const* d_in, const int* in_sizes, int n_in,
                              void* d_out, int out_size) {
    const float* x   = (const float*)d_in[0];
    const int*   ei  = (const int*)d_in[1];
    const int*   et  = (const int*)d_in[2];
    const float* W1  = (const float*)d_in[3];
    const float* q1  = (const float*)d_in[4];
    const float* k1  = (const float*)d_in[5];
    const float* b1  = (const float*)d_in[6];
    const float* Wmu = (const float*)d_in[7];
    const float* qmu = (const float*)d_in[8];
    const float* kmu = (const float*)d_in[9];
    const float* bmu = (const float*)d_in[10];
    const float* Wlv = (const float*)d_in[11];
    const float* qlv = (const float*)d_in[12];
    const float* klv = (const float*)d_in[13];
    const float* blv = (const float*)d_in[14];
    const float* Wm  = (const float*)d_in[15];
    const float* bm  = (const float*)d_in[16];
    const float* Wl  = (const float*)d_in[17];
    const float* bl  = (const float*)d_in[18];
    const int* src = ei;
    const int* dst = ei + EE;
    float* out = (float*)d_out;

    float*  hidden; cudaGetSymbolAddress((void**)&hidden, g_hidden);
    __half* ta;     cudaGetSymbolAddress((void**)&ta, g_ta);
    __half* tc;     cudaGetSymbolAddress((void**)&tc, g_tc);
    int*    offp;   cudaGetSymbolAddress((void**)&offp, g_off);

    static cudaStream_t s1 = nullptr, s2 = nullptr;
    static cudaEvent_t evFork, evCSR, evHid, evQd2, evQd1;
    if (!s1) {
        cudaStreamCreateWithFlags(&s1, cudaStreamNonBlocking);
        cudaStreamCreateWithFlags(&s2, cudaStreamNonBlocking);
        cudaEventCreateWithFlags(&evFork, cudaEventDisableTiming);
        cudaEventCreateWithFlags(&evCSR,  cudaEventDisableTiming);
        cudaEventCreateWithFlags(&evHid,  cudaEventDisableTiming);
        cudaEventCreateWithFlags(&evQd2,  cudaEventDisableTiming);
        cudaEventCreateWithFlags(&evQd1,  cudaEventDisableTiming);
    }

    const int TB = 256;
    dim3 gemm_grid((NN + BM - 1) / BM, RR);
    int node_warp_blocks = (NN + 7) / 8;

    // ---- fork: CSR on s1; wqwk3->qdkd on s2; gemm1 immediately on main ----
    cudaEventRecord(evFork, 0);
    cudaStreamWaitEvent(s1, evFork, 0);
    cudaStreamWaitEvent(s2, evFork, 0);
    cudaMemsetAsync(offp, 0, (NN + 1) * sizeof(int), s1);
    k_wqwk3<<<3, TB, 0, s2>>>(W1, q1, k1, Wmu, qmu, kmu, Wlv, qlv, klv);
    k_qdkd<<<node_warp_blocks, TB, 0, s2>>>(x, DIN1);
    cudaEventRecord(evQd1, s2);

    k_gemm<<<gemm_grid, TB>>>(x, W1, ta, DIN1);

    k_hist<<<EE / TB, TB, 0, s1>>>(dst);
    k_scan<<<1, 1024, 0, s1>>>();
    k_scatter<<<EE / TB, TB, 0, s1>>>(src, dst, et);
    cudaEventRecord(evCSR, s1);

    // ---- join CSR + qdkd1, layer-1 aggregation ----
    cudaStreamWaitEvent(0, evCSR, 0);
    cudaStreamWaitEvent(0, evQd1, 0);
    k_agg<<<node_warp_blocks, TB>>>(ta, b1, hidden);
    cudaEventRecord(evHid, 0);

    // ---- qdkd2 on s1, concurrent with gemm2 ----
    cudaStreamWaitEvent(s1, evHid, 0);
    k_qdkd2<<<node_warp_blocks, TB, 0, s1>>>(hidden);
    cudaEventRecord(evQd2, s1);

    k_gemm2<<<gemm_grid, TB>>>(hidden, Wmu, Wlv, tc);
    cudaStreamWaitEvent(0, evQd2, 0);
    k_agg2<<<(NN + 31) / 32, TB>>>(tc, bmu, blv, Wm, bm, Wl, bl, out);
}